// round 1
// baseline (speedup 1.0000x reference)
#include <cuda_runtime.h>
#include <cstddef>

#define H 64
#define NGn 100000
#define NDn 30000

// -------- scratch (device globals; no allocation allowed) --------
__device__ float g_msum_g[(size_t)NGn * H];
__device__ float g_msum_d[(size_t)NDn * H];
__device__ float g_cnt_g[NGn];
__device__ float g_cnt_d[NDn];
__device__ float g_hg [(size_t)NGn * H];
__device__ float g_hd [(size_t)NDn * H];
__device__ float g_hg2[(size_t)NGn * H];
__device__ float g_hd2[(size_t)NDn * H];

// -------- zero kernel (float4) --------
__global__ void zero_kernel(float4* p, int n4) {
    int i = blockIdx.x * blockDim.x + threadIdx.x;
    if (i < n4) p[i] = make_float4(0.f, 0.f, 0.f, 0.f);
}

// -------- fused bidirectional mean-sum aggregation --------
// 16 lanes per edge; each lane moves 4 floats (float4) per direction.
// msd[dst] += xg[src];  msg[src] += xd[dst];  (+ counts on first pass)
__global__ __launch_bounds__(256) void agg_kernel(
    const float* __restrict__ xg, const float* __restrict__ xd,
    const int* __restrict__ src, const int* __restrict__ dst,
    float* __restrict__ msd, float* __restrict__ msg,
    float* __restrict__ cg, float* __restrict__ cd,
    int ne, int do_cnt)
{
    int t = blockIdx.x * blockDim.x + threadIdx.x;
    int e = t >> 4;
    if (e >= ne) return;
    int lane = t & 15;
    int s = src[e];
    int d = dst[e];

    const float4 a = *(const float4*)(xg + (size_t)s * H + lane * 4);
    const float4 b = *(const float4*)(xd + (size_t)d * H + lane * 4);
    float* pd = msd + (size_t)d * H + lane * 4;
    float* pg = msg + (size_t)s * H + lane * 4;

    asm volatile("red.global.add.v4.f32 [%0], {%1,%2,%3,%4};"
                 :: "l"(pd), "f"(a.x), "f"(a.y), "f"(a.z), "f"(a.w) : "memory");
    asm volatile("red.global.add.v4.f32 [%0], {%1,%2,%3,%4};"
                 :: "l"(pg), "f"(b.x), "f"(b.y), "f"(b.z), "f"(b.w) : "memory");

    if (do_cnt && lane == 0) {
        atomicAdd(cd + d, 1.0f);
        atomicAdd(cg + s, 1.0f);
    }
}

// -------- SAGE linear:  out = [relu]( (msum/max(cnt,1)) @ wl + xdst @ wr + b ) --------
// block: 16x16. Each thread computes 4 output columns for one row; 16 rows / tile.
__global__ __launch_bounds__(256) void sage_lin(
    const float* __restrict__ msum, const float* __restrict__ cnt,
    const float* __restrict__ xdst,
    const float* __restrict__ wl, const float* __restrict__ wr,
    const float* __restrict__ bias,
    float* __restrict__ out, int n, int relu)
{
    __shared__ __align__(16) float sWl[H * H];
    __shared__ __align__(16) float sWr[H * H];
    __shared__ float sB[H];
    __shared__ __align__(16) float sM[16][H];
    __shared__ __align__(16) float sX[16][H];

    int tx = threadIdx.x;            // 0..15 -> 4 cols each
    int ty = threadIdx.y;            // 0..15 -> row in tile
    int tid = ty * 16 + tx;

    for (int i = tid; i < H * H; i += 256) { sWl[i] = wl[i]; sWr[i] = wr[i]; }
    if (tid < H) sB[tid] = bias[tid];
    __syncthreads();

    for (int tile = blockIdx.x; tile * 16 < n; tile += gridDim.x) {
        int row = tile * 16 + ty;
        bool valid = row < n;
        // stage this tile's mean and x rows
        if (valid) {
            float c = cnt[row];
            float inv = 1.0f / fmaxf(c, 1.0f);
            float4 mv = *(const float4*)(msum + (size_t)row * H + tx * 4);
            mv.x *= inv; mv.y *= inv; mv.z *= inv; mv.w *= inv;
            *(float4*)&sM[ty][tx * 4] = mv;
            *(float4*)&sX[ty][tx * 4] = *(const float4*)(xdst + (size_t)row * H + tx * 4);
        } else {
            *(float4*)&sM[ty][tx * 4] = make_float4(0.f, 0.f, 0.f, 0.f);
            *(float4*)&sX[ty][tx * 4] = make_float4(0.f, 0.f, 0.f, 0.f);
        }
        __syncthreads();

        float a0 = sB[tx * 4 + 0], a1 = sB[tx * 4 + 1],
              a2 = sB[tx * 4 + 2], a3 = sB[tx * 4 + 3];
        #pragma unroll 8
        for (int k = 0; k < H; k++) {
            float m = sM[ty][k];
            float x = sX[ty][k];
            float4 wlv = *(const float4*)&sWl[k * H + tx * 4];
            float4 wrv = *(const float4*)&sWr[k * H + tx * 4];
            a0 += m * wlv.x + x * wrv.x;
            a1 += m * wlv.y + x * wrv.y;
            a2 += m * wlv.z + x * wrv.z;
            a3 += m * wlv.w + x * wrv.w;
        }
        if (relu) {
            a0 = fmaxf(a0, 0.f); a1 = fmaxf(a1, 0.f);
            a2 = fmaxf(a2, 0.f); a3 = fmaxf(a3, 0.f);
        }
        if (valid) {
            *(float4*)(out + (size_t)row * H + tx * 4) = make_float4(a0, a1, a2, a3);
        }
        __syncthreads();
    }
}

// -------- label-edge dot product: out[e] = <hg2[ls[e]], hd2[ld[e]]> --------
// 8 lanes per edge; each lane handles 2 float4 chunks, then shuffle-reduce.
__global__ __launch_bounds__(256) void dot_kernel(
    const float* __restrict__ hg2, const float* __restrict__ hd2,
    const int* __restrict__ ls, const int* __restrict__ ld,
    float* __restrict__ out, int nl)
{
    int t = blockIdx.x * blockDim.x + threadIdx.x;
    int e = t >> 3;
    if (e >= nl) return;
    int lane = t & 7;
    int a = ls[e];
    int b = ld[e];
    const float4* pg = (const float4*)(hg2 + (size_t)a * H);
    const float4* pd = (const float4*)(hd2 + (size_t)b * H);

    float4 g0 = pg[lane], d0 = pd[lane];
    float4 g1 = pg[lane + 8], d1 = pd[lane + 8];
    float acc = g0.x * d0.x + g0.y * d0.y + g0.z * d0.z + g0.w * d0.w
              + g1.x * d1.x + g1.y * d1.y + g1.z * d1.z + g1.w * d1.w;

    acc += __shfl_down_sync(0xFFFFFFFFu, acc, 4);
    acc += __shfl_down_sync(0xFFFFFFFFu, acc, 2);
    acc += __shfl_down_sync(0xFFFFFFFFu, acc, 1);
    if (lane == 0) out[e] = acc;
}

static inline void zero_buf(float* p, size_t n) {
    int n4 = (int)(n / 4);
    zero_kernel<<<(n4 + 255) / 256, 256>>>((float4*)p, n4);
}

extern "C" void kernel_launch(void* const* d_in, const int* in_sizes, int n_in,
                              void* d_out, int out_size)
{
    // ---- identify inputs by element count (robust to metadata ordering) ----
    const float* gene = nullptr;
    const float* dis  = nullptr;
    const float* w[8] = {};   // w1_gd_l, w1_gd_r, w1_dg_l, w1_dg_r, w2_gd_l, w2_gd_r, w2_dg_l, w2_dg_r
    const float* b[4] = {};   // b1_gd, b1_dg, b2_gd, b2_dg
    const int*   edge[2] = {};   // edge_src, edge_dst
    const int*   lab[2]  = {};   // label_src, label_dst
    int wi = 0, bi = 0, ei = 0, li = 0;
    int ne = 0, nl = 0;

    for (int i = 0; i < n_in; i++) {
        int sz = in_sizes[i];
        if (sz == NGn * H)          gene = (const float*)d_in[i];
        else if (sz == NDn * H)     dis  = (const float*)d_in[i];
        else if (sz == H * H)       { if (wi < 8) w[wi++] = (const float*)d_in[i]; }
        else if (sz == H)           { if (bi < 4) b[bi++] = (const float*)d_in[i]; }
        else if (sz == 1500000)     { if (ei < 2) { edge[ei++] = (const int*)d_in[i]; ne = sz; } }
        else if (sz == 500000)      { if (li < 2) { lab[li++]  = (const int*)d_in[i]; nl = sz; } }
    }

    // ---- scratch pointers ----
    float *msg, *msd, *cg, *cd, *hg, *hd, *hg2, *hd2;
    cudaGetSymbolAddress((void**)&msg, g_msum_g);
    cudaGetSymbolAddress((void**)&msd, g_msum_d);
    cudaGetSymbolAddress((void**)&cg,  g_cnt_g);
    cudaGetSymbolAddress((void**)&cd,  g_cnt_d);
    cudaGetSymbolAddress((void**)&hg,  g_hg);
    cudaGetSymbolAddress((void**)&hd,  g_hd);
    cudaGetSymbolAddress((void**)&hg2, g_hg2);
    cudaGetSymbolAddress((void**)&hd2, g_hd2);

    const int AGG_THREADS = 256;
    int agg_grid = (ne * 16 + AGG_THREADS - 1) / AGG_THREADS;
    dim3 linBlk(16, 16);
    const int LIN_GRID = 1184;   // 8 blocks/SM worth of tiles, grid-stride over rows

    // ---- layer 1 ----
    zero_buf(msg, (size_t)NGn * H);
    zero_buf(msd, (size_t)NDn * H);
    zero_buf(cg, NGn);
    zero_buf(cd, NDn);

    agg_kernel<<<agg_grid, AGG_THREADS>>>(gene, dis, edge[0], edge[1],
                                          msd, msg, cg, cd, ne, 1);

    sage_lin<<<LIN_GRID, linBlk>>>(msd, cd, dis,  w[0], w[1], b[0], hd, NDn, 1);
    sage_lin<<<LIN_GRID, linBlk>>>(msg, cg, gene, w[2], w[3], b[1], hg, NGn, 1);

    // ---- layer 2 ----
    zero_buf(msg, (size_t)NGn * H);
    zero_buf(msd, (size_t)NDn * H);

    agg_kernel<<<agg_grid, AGG_THREADS>>>(hg, hd, edge[0], edge[1],
                                          msd, msg, cg, cd, ne, 0);

    sage_lin<<<LIN_GRID, linBlk>>>(msd, cd, hd, w[4], w[5], b[2], hd2, NDn, 0);
    sage_lin<<<LIN_GRID, linBlk>>>(msg, cg, hg, w[6], w[7], b[3], hg2, NGn, 0);

    // ---- classifier ----
    int dot_grid = (nl * 8 + 255) / 256;
    dot_kernel<<<dot_grid, 256>>>(hg2, hd2, lab[0], lab[1], (float*)d_out, nl);
}

// round 2
// speedup vs baseline: 1.5739x; 1.5739x over previous
#include <cuda_runtime.h>
#include <cstddef>

#define H 64
#define NGn 100000
#define NDn 30000
#define Mn (NGn + NDn)          // 130000 combined nodes (gene region first)
#define NEmax 1500000
#define SCAN_B 1024
#define NBLK ((Mn + SCAN_B - 1) / SCAN_B)   // 127

// -------- scratch (device globals; no allocation allowed) --------
__device__ int   g_deg [Mn];
__device__ int   g_incl[Mn];
__device__ int   g_off [Mn + 1];
__device__ int   g_cur [Mn];
__device__ int   g_part[256];
__device__ int   g_adj [2 * NEmax];
__device__ float g_meanG[(size_t)NGn * H];   // per-gene mean of neighbor (disease-side) rows
__device__ float g_meanD[(size_t)NDn * H];   // per-disease mean of neighbor (gene-side) rows
__device__ float g_hg [(size_t)NGn * H];
__device__ float g_hd [(size_t)NDn * H];
__device__ float g_hg2[(size_t)NGn * H];
__device__ float g_hd2[(size_t)NDn * H];

// -------- zero (int4) --------
__global__ void zero_i4(int4* p, int n4) {
    int i = blockIdx.x * blockDim.x + threadIdx.x;
    if (i < n4) p[i] = make_int4(0, 0, 0, 0);
}

// -------- degree histogram (combined node space) --------
__global__ void hist_kernel(const int* __restrict__ src, const int* __restrict__ dst,
                            int* __restrict__ deg, int ne) {
    int e = blockIdx.x * blockDim.x + threadIdx.x;
    if (e >= ne) return;
    atomicAdd(&deg[src[e]], 1);
    atomicAdd(&deg[NGn + dst[e]], 1);
}

// -------- scan stage 1: per-block inclusive scan + block totals --------
__global__ __launch_bounds__(1024) void scan1(const int* __restrict__ deg,
                                              int* __restrict__ incl,
                                              int* __restrict__ part, int n) {
    __shared__ int ws[32];
    int i = blockIdx.x * SCAN_B + threadIdx.x;
    int v = (i < n) ? deg[i] : 0;
    int x = v;
    #pragma unroll
    for (int o = 1; o < 32; o <<= 1) {
        int y = __shfl_up_sync(0xFFFFFFFFu, x, o);
        if ((threadIdx.x & 31) >= o) x += y;
    }
    if ((threadIdx.x & 31) == 31) ws[threadIdx.x >> 5] = x;
    __syncthreads();
    if (threadIdx.x < 32) {
        int y = ws[threadIdx.x];
        #pragma unroll
        for (int o = 1; o < 32; o <<= 1) {
            int z = __shfl_up_sync(0xFFFFFFFFu, y, o);
            if (threadIdx.x >= o) y += z;
        }
        ws[threadIdx.x] = y;
    }
    __syncthreads();
    if (threadIdx.x >= 32) x += ws[(threadIdx.x >> 5) - 1];
    if (i < n) incl[i] = x;
    if (threadIdx.x == 1023) part[blockIdx.x] = x;
}

// -------- scan stage 2: exclusive-scan the block totals (single block, 128 thr) --------
__global__ void scan2(int* __restrict__ part, int nb) {
    __shared__ int ws[4];
    int t = threadIdx.x;
    int v = (t < nb) ? part[t] : 0;
    int x = v;
    #pragma unroll
    for (int o = 1; o < 32; o <<= 1) {
        int y = __shfl_up_sync(0xFFFFFFFFu, x, o);
        if ((t & 31) >= o) x += y;
    }
    if ((t & 31) == 31) ws[t >> 5] = x;
    __syncthreads();
    int add = 0;
    for (int w = 0; w < (t >> 5); w++) add += ws[w];
    x += add;
    if (t < nb) part[t] = x - v;   // exclusive
}

// -------- scan stage 3: finalize offsets + cursors --------
__global__ void scan3(const int* __restrict__ incl, const int* __restrict__ deg,
                      const int* __restrict__ part,
                      int* __restrict__ off, int* __restrict__ cur, int n) {
    int i = blockIdx.x * blockDim.x + threadIdx.x;
    if (i >= n) return;
    int inc = incl[i] + part[i / SCAN_B];
    off[i + 1] = inc;
    cur[i] = inc - deg[i];
    if (i == 0) off[0] = 0;
}

// -------- scatter edges into combined adjacency --------
__global__ void scatter_kernel(const int* __restrict__ src, const int* __restrict__ dst,
                               int* __restrict__ cur, int* __restrict__ adj, int ne) {
    int e = blockIdx.x * blockDim.x + threadIdx.x;
    if (e >= ne) return;
    int s = src[e], d = dst[e];
    int p = atomicAdd(&cur[s], 1);        adj[p] = d;       // gene node -> disease nbr
    int q = atomicAdd(&cur[NGn + d], 1);  adj[q] = s;       // disease node -> gene nbr
}

// -------- warp-per-node gather-mean (both directions in one launch) --------
// gene node w < NGn aggregates xd rows; disease node aggregates xg rows.
__global__ __launch_bounds__(256) void gather_kernel(
    const float2* __restrict__ xg, const float2* __restrict__ xd,
    const int* __restrict__ off, const int* __restrict__ adj,
    float2* __restrict__ outG, float2* __restrict__ outD)
{
    int w = (blockIdx.x * blockDim.x + threadIdx.x) >> 5;
    if (w >= Mn) return;
    int lane = threadIdx.x & 31;
    int beg = off[w], end = off[w + 1];
    const float2* __restrict__ x = (w < NGn) ? xd : xg;

    float2 a0 = {0.f, 0.f}, a1 = {0.f, 0.f}, a2 = {0.f, 0.f}, a3 = {0.f, 0.f};
    int j = beg;
    for (; j + 4 <= end; j += 4) {
        int n0 = __ldg(&adj[j + 0]);
        int n1 = __ldg(&adj[j + 1]);
        int n2 = __ldg(&adj[j + 2]);
        int n3 = __ldg(&adj[j + 3]);
        float2 v0 = x[(size_t)n0 * 32 + lane];
        float2 v1 = x[(size_t)n1 * 32 + lane];
        float2 v2 = x[(size_t)n2 * 32 + lane];
        float2 v3 = x[(size_t)n3 * 32 + lane];
        a0.x += v0.x; a0.y += v0.y;
        a1.x += v1.x; a1.y += v1.y;
        a2.x += v2.x; a2.y += v2.y;
        a3.x += v3.x; a3.y += v3.y;
    }
    for (; j < end; j++) {
        int nn = __ldg(&adj[j]);
        float2 v = x[(size_t)nn * 32 + lane];
        a0.x += v.x; a0.y += v.y;
    }
    float2 s;
    s.x = (a0.x + a1.x) + (a2.x + a3.x);
    s.y = (a0.y + a1.y) + (a2.y + a3.y);
    float inv = 1.0f / fmaxf((float)(end - beg), 1.0f);
    s.x *= inv; s.y *= inv;
    if (w < NGn) outG[(size_t)w * 32 + lane] = s;
    else         outD[(size_t)(w - NGn) * 32 + lane] = s;
}

// -------- SAGE linear: out = [relu]( mean @ wl + x @ wr + b ) --------
// 32-row tiles, block(16,16); each thread: 2 rows x 4 cols. 48KB static smem.
__global__ __launch_bounds__(256) void sage_lin(
    const float* __restrict__ mean, const float* __restrict__ xdst,
    const float* __restrict__ wl, const float* __restrict__ wr,
    const float* __restrict__ bias,
    float* __restrict__ out, int n, int relu)
{
    __shared__ __align__(16) float sWl[H * H];
    __shared__ __align__(16) float sWr[H * H];
    __shared__ __align__(16) float sM[32][H];
    __shared__ __align__(16) float sX[32][H];

    int tx = threadIdx.x;           // 0..15 -> 4 output cols
    int ty = threadIdx.y;           // 0..15 -> 2 rows
    int tid = ty * 16 + tx;

    for (int i = tid * 4; i < H * H; i += 1024) {
        *(float4*)&sWl[i] = *(const float4*)&wl[i];
        *(float4*)&sWr[i] = *(const float4*)&wr[i];
    }
    float4 bv = *(const float4*)&bias[tx * 4];

    int r0 = blockIdx.x * 32;

    // stage 32 rows of mean & x (512 float4 each)
    for (int i = tid; i < 32 * 16; i += 256) {
        int row = i >> 4, c4 = i & 15;
        int gr = r0 + row;
        float4 mv, xv;
        if (gr < n) {
            mv = *(const float4*)&mean[(size_t)gr * H + c4 * 4];
            xv = *(const float4*)&xdst[(size_t)gr * H + c4 * 4];
        } else {
            mv = make_float4(0.f, 0.f, 0.f, 0.f);
            xv = mv;
        }
        *(float4*)&sM[row][c4 * 4] = mv;
        *(float4*)&sX[row][c4 * 4] = xv;
    }
    __syncthreads();

    float4 acc0 = bv, acc1 = bv;
    int ra = ty * 2, rb = ty * 2 + 1;
    #pragma unroll 16
    for (int k = 0; k < H; k++) {
        float4 wlv = *(const float4*)&sWl[k * H + tx * 4];
        float4 wrv = *(const float4*)&sWr[k * H + tx * 4];
        float m0 = sM[ra][k], x0 = sX[ra][k];
        float m1 = sM[rb][k], x1 = sX[rb][k];
        acc0.x += m0 * wlv.x + x0 * wrv.x;
        acc0.y += m0 * wlv.y + x0 * wrv.y;
        acc0.z += m0 * wlv.z + x0 * wrv.z;
        acc0.w += m0 * wlv.w + x0 * wrv.w;
        acc1.x += m1 * wlv.x + x1 * wrv.x;
        acc1.y += m1 * wlv.y + x1 * wrv.y;
        acc1.z += m1 * wlv.z + x1 * wrv.z;
        acc1.w += m1 * wlv.w + x1 * wrv.w;
    }
    if (relu) {
        acc0.x = fmaxf(acc0.x, 0.f); acc0.y = fmaxf(acc0.y, 0.f);
        acc0.z = fmaxf(acc0.z, 0.f); acc0.w = fmaxf(acc0.w, 0.f);
        acc1.x = fmaxf(acc1.x, 0.f); acc1.y = fmaxf(acc1.y, 0.f);
        acc1.z = fmaxf(acc1.z, 0.f); acc1.w = fmaxf(acc1.w, 0.f);
    }
    int g0 = r0 + ra, g1 = r0 + rb;
    if (g0 < n) *(float4*)&out[(size_t)g0 * H + tx * 4] = acc0;
    if (g1 < n) *(float4*)&out[(size_t)g1 * H + tx * 4] = acc1;
}

// -------- label-edge dot product --------
__global__ __launch_bounds__(256) void dot_kernel(
    const float* __restrict__ hg2, const float* __restrict__ hd2,
    const int* __restrict__ ls, const int* __restrict__ ld,
    float* __restrict__ out, int nl)
{
    int t = blockIdx.x * blockDim.x + threadIdx.x;
    int e = t >> 3;
    if (e >= nl) return;
    int lane = t & 7;
    int a = ls[e];
    int b = ld[e];
    const float4* pg = (const float4*)(hg2 + (size_t)a * H);
    const float4* pd = (const float4*)(hd2 + (size_t)b * H);

    float4 g0 = pg[lane], d0 = pd[lane];
    float4 g1 = pg[lane + 8], d1 = pd[lane + 8];
    float acc = g0.x * d0.x + g0.y * d0.y + g0.z * d0.z + g0.w * d0.w
              + g1.x * d1.x + g1.y * d1.y + g1.z * d1.z + g1.w * d1.w;

    acc += __shfl_down_sync(0xFFFFFFFFu, acc, 4);
    acc += __shfl_down_sync(0xFFFFFFFFu, acc, 2);
    acc += __shfl_down_sync(0xFFFFFFFFu, acc, 1);
    if (lane == 0) out[e] = acc;
}

extern "C" void kernel_launch(void* const* d_in, const int* in_sizes, int n_in,
                              void* d_out, int out_size)
{
    // ---- identify inputs by element count ----
    const float* gene = nullptr;
    const float* dis  = nullptr;
    const float* w[8] = {};   // w1_gd_l, w1_gd_r, w1_dg_l, w1_dg_r, w2_gd_l, w2_gd_r, w2_dg_l, w2_dg_r
    const float* b[4] = {};   // b1_gd, b1_dg, b2_gd, b2_dg
    const int*   edge[2] = {};
    const int*   lab[2]  = {};
    int wi = 0, bi = 0, ei = 0, li = 0;
    int ne = 0, nl = 0;

    for (int i = 0; i < n_in; i++) {
        int sz = in_sizes[i];
        if (sz == NGn * H)          gene = (const float*)d_in[i];
        else if (sz == NDn * H)     dis  = (const float*)d_in[i];
        else if (sz == H * H)       { if (wi < 8) w[wi++] = (const float*)d_in[i]; }
        else if (sz == H)           { if (bi < 4) b[bi++] = (const float*)d_in[i]; }
        else if (sz == 1500000)     { if (ei < 2) { edge[ei++] = (const int*)d_in[i]; ne = sz; } }
        else if (sz == 500000)      { if (li < 2) { lab[li++]  = (const int*)d_in[i]; nl = sz; } }
    }

    // ---- scratch pointers ----
    int *deg, *incl, *off, *cur, *part, *adj;
    float *mG, *mD, *hg, *hd, *hg2, *hd2;
    cudaGetSymbolAddress((void**)&deg,  g_deg);
    cudaGetSymbolAddress((void**)&incl, g_incl);
    cudaGetSymbolAddress((void**)&off,  g_off);
    cudaGetSymbolAddress((void**)&cur,  g_cur);
    cudaGetSymbolAddress((void**)&part, g_part);
    cudaGetSymbolAddress((void**)&adj,  g_adj);
    cudaGetSymbolAddress((void**)&mG,   g_meanG);
    cudaGetSymbolAddress((void**)&mD,   g_meanD);
    cudaGetSymbolAddress((void**)&hg,   g_hg);
    cudaGetSymbolAddress((void**)&hd,   g_hd);
    cudaGetSymbolAddress((void**)&hg2,  g_hg2);
    cudaGetSymbolAddress((void**)&hd2,  g_hd2);

    int egrid = (ne + 255) / 256;
    int ggrid = (Mn * 32 + 255) / 256;
    dim3 linBlk(16, 16);

    // ---- CSR build (reused by both layers) ----
    zero_i4<<<(Mn / 4 + 255) / 256, 256>>>((int4*)deg, Mn / 4);
    hist_kernel<<<egrid, 256>>>(edge[0], edge[1], deg, ne);
    scan1<<<NBLK, 1024>>>(deg, incl, part, Mn);
    scan2<<<1, 128>>>(part, NBLK);
    scan3<<<(Mn + 255) / 256, 256>>>(incl, deg, part, off, cur, Mn);
    scatter_kernel<<<egrid, 256>>>(edge[0], edge[1], cur, adj, ne);

    // ---- layer 1 ----
    gather_kernel<<<ggrid, 256>>>((const float2*)gene, (const float2*)dis,
                                  off, adj, (float2*)mG, (float2*)mD);
    sage_lin<<<(NDn + 31) / 32, linBlk>>>(mD, dis,  w[0], w[1], b[0], hd, NDn, 1);
    sage_lin<<<(NGn + 31) / 32, linBlk>>>(mG, gene, w[2], w[3], b[1], hg, NGn, 1);

    // ---- layer 2 ----
    gather_kernel<<<ggrid, 256>>>((const float2*)hg, (const float2*)hd,
                                  off, adj, (float2*)mG, (float2*)mD);
    sage_lin<<<(NDn + 31) / 32, linBlk>>>(mD, hd, w[4], w[5], b[2], hd2, NDn, 0);
    sage_lin<<<(NGn + 31) / 32, linBlk>>>(mG, hg, w[6], w[7], b[3], hg2, NGn, 0);

    // ---- classifier ----
    int dot_grid = (nl * 8 + 255) / 256;
    dot_kernel<<<dot_grid, 256>>>(hg2, hd2, lab[0], lab[1], (float*)d_out, nl);
}

// round 3
// speedup vs baseline: 1.8657x; 1.1854x over previous
#include <cuda_runtime.h>
#include <cuda_fp16.h>
#include <cstddef>
#include <cstdint>

#define H 64
#define NGn 100000
#define NDn 30000
#define Mn (NGn + NDn)
#define NEmax 1500000
#define SCAN_B 1024
#define NBLK ((Mn + SCAN_B - 1) / SCAN_B)

// -------- scratch --------
__device__ int   g_deg [Mn];
__device__ int   g_incl[Mn];
__device__ int   g_off [Mn + 1];
__device__ int   g_cur [Mn];
__device__ int   g_part[256];
__device__ int   g_adj [2 * NEmax];
__device__ float g_meanG[(size_t)NGn * H];
__device__ float g_meanD[(size_t)NDn * H];
__device__ float g_hg [(size_t)NGn * H];
__device__ float g_hd [(size_t)NDn * H];
__device__ float g_hg2[(size_t)NGn * H];
__device__ float g_hd2[(size_t)NDn * H];
__device__ __half2 g_geneH[(size_t)NGn * 32];
__device__ __half2 g_disH [(size_t)NDn * 32];
__device__ __half2 g_hgH  [(size_t)NGn * 32];
__device__ __half2 g_hdH  [(size_t)NDn * 32];

// -------- helpers --------
__device__ __forceinline__ uint32_t f2tf32(float f) {
    uint32_t u;
    asm("cvt.rna.tf32.f32 %0, %1;" : "=r"(u) : "f"(f));
    return u;
}
__device__ __forceinline__ void mma8(float c[4],
                                     uint32_t a0, uint32_t a1, uint32_t a2, uint32_t a3,
                                     uint32_t b0, uint32_t b1) {
    asm volatile(
        "mma.sync.aligned.m16n8k8.row.col.f32.tf32.tf32.f32 "
        "{%0,%1,%2,%3},{%4,%5,%6,%7},{%8,%9},{%0,%1,%2,%3};"
        : "+f"(c[0]), "+f"(c[1]), "+f"(c[2]), "+f"(c[3])
        : "r"(a0), "r"(a1), "r"(a2), "r"(a3), "r"(b0), "r"(b1));
}

// -------- zero (int4) --------
__global__ void zero_i4(int4* p, int n4) {
    int i = blockIdx.x * blockDim.x + threadIdx.x;
    if (i < n4) p[i] = make_int4(0, 0, 0, 0);
}

// -------- fp32 -> half2 conversion --------
__global__ void f2h_kernel(const float2* __restrict__ in, __half2* __restrict__ out, int n2) {
    int i = blockIdx.x * blockDim.x + threadIdx.x;
    if (i < n2) {
        float2 v = in[i];
        out[i] = __floats2half2_rn(v.x, v.y);
    }
}

// -------- CSR build --------
__global__ void hist_kernel(const int* __restrict__ src, const int* __restrict__ dst,
                            int* __restrict__ deg, int ne) {
    int e = blockIdx.x * blockDim.x + threadIdx.x;
    if (e >= ne) return;
    atomicAdd(&deg[src[e]], 1);
    atomicAdd(&deg[NGn + dst[e]], 1);
}

__global__ __launch_bounds__(1024) void scan1(const int* __restrict__ deg,
                                              int* __restrict__ incl,
                                              int* __restrict__ part, int n) {
    __shared__ int ws[32];
    int i = blockIdx.x * SCAN_B + threadIdx.x;
    int v = (i < n) ? deg[i] : 0;
    int x = v;
    #pragma unroll
    for (int o = 1; o < 32; o <<= 1) {
        int y = __shfl_up_sync(0xFFFFFFFFu, x, o);
        if ((threadIdx.x & 31) >= o) x += y;
    }
    if ((threadIdx.x & 31) == 31) ws[threadIdx.x >> 5] = x;
    __syncthreads();
    if (threadIdx.x < 32) {
        int y = ws[threadIdx.x];
        #pragma unroll
        for (int o = 1; o < 32; o <<= 1) {
            int z = __shfl_up_sync(0xFFFFFFFFu, y, o);
            if (threadIdx.x >= o) y += z;
        }
        ws[threadIdx.x] = y;
    }
    __syncthreads();
    if (threadIdx.x >= 32) x += ws[(threadIdx.x >> 5) - 1];
    if (i < n) incl[i] = x;
    if (threadIdx.x == 1023) part[blockIdx.x] = x;
}

__global__ void scan2(int* __restrict__ part, int nb) {
    __shared__ int ws[4];
    int t = threadIdx.x;
    int v = (t < nb) ? part[t] : 0;
    int x = v;
    #pragma unroll
    for (int o = 1; o < 32; o <<= 1) {
        int y = __shfl_up_sync(0xFFFFFFFFu, x, o);
        if ((t & 31) >= o) x += y;
    }
    if ((t & 31) == 31) ws[t >> 5] = x;
    __syncthreads();
    int add = 0;
    for (int w = 0; w < (t >> 5); w++) add += ws[w];
    x += add;
    if (t < nb) part[t] = x - v;
}

__global__ void scan3(const int* __restrict__ incl, const int* __restrict__ deg,
                      const int* __restrict__ part,
                      int* __restrict__ off, int* __restrict__ cur, int n) {
    int i = blockIdx.x * blockDim.x + threadIdx.x;
    if (i >= n) return;
    int inc = incl[i] + part[i / SCAN_B];
    off[i + 1] = inc;
    cur[i] = inc - deg[i];
    if (i == 0) off[0] = 0;
}

__global__ void scatter_kernel(const int* __restrict__ src, const int* __restrict__ dst,
                               int* __restrict__ cur, int* __restrict__ adj, int ne) {
    int e = blockIdx.x * blockDim.x + threadIdx.x;
    if (e >= ne) return;
    int s = src[e], d = dst[e];
    int p = atomicAdd(&cur[s], 1);        adj[p] = d;
    int q = atomicAdd(&cur[NGn + d], 1);  adj[q] = s;
}

// -------- warp-per-node gather-mean, fp16 input, fp32 accum --------
__global__ __launch_bounds__(256) void gather_h(
    const __half2* __restrict__ xg, const __half2* __restrict__ xd,
    const int* __restrict__ off, const int* __restrict__ adj,
    float2* __restrict__ outG, float2* __restrict__ outD)
{
    int w = (blockIdx.x * blockDim.x + threadIdx.x) >> 5;
    if (w >= Mn) return;
    int lane = threadIdx.x & 31;
    int beg = off[w], end = off[w + 1];
    const __half2* __restrict__ x = (w < NGn) ? xd : xg;

    float2 a0 = {0.f, 0.f}, a1 = {0.f, 0.f}, a2 = {0.f, 0.f}, a3 = {0.f, 0.f};
    int j = beg;
    for (; j + 4 <= end; j += 4) {
        int n0 = __ldg(&adj[j + 0]);
        int n1 = __ldg(&adj[j + 1]);
        int n2 = __ldg(&adj[j + 2]);
        int n3 = __ldg(&adj[j + 3]);
        float2 v0 = __half22float2(x[(size_t)n0 * 32 + lane]);
        float2 v1 = __half22float2(x[(size_t)n1 * 32 + lane]);
        float2 v2 = __half22float2(x[(size_t)n2 * 32 + lane]);
        float2 v3 = __half22float2(x[(size_t)n3 * 32 + lane]);
        a0.x += v0.x; a0.y += v0.y;
        a1.x += v1.x; a1.y += v1.y;
        a2.x += v2.x; a2.y += v2.y;
        a3.x += v3.x; a3.y += v3.y;
    }
    for (; j < end; j++) {
        int nn = __ldg(&adj[j]);
        float2 v = __half22float2(x[(size_t)nn * 32 + lane]);
        a0.x += v.x; a0.y += v.y;
    }
    float2 s;
    s.x = (a0.x + a1.x) + (a2.x + a3.x);
    s.y = (a0.y + a1.y) + (a2.y + a3.y);
    float inv = 1.0f / fmaxf((float)(end - beg), 1.0f);
    s.x *= inv; s.y *= inv;
    if (w < NGn) outG[(size_t)w * 32 + lane] = s;
    else         outD[(size_t)(w - NGn) * 32 + lane] = s;
}

// -------- SAGE linear via tf32 mma.sync --------
// out = [relu]( mean @ wl + x @ wr + b );  optional fp16 copy (out_h).
// Block 256 = 8 warps, each warp computes 16 rows x 64 cols. 128 rows/block.
// W = [wl; wr] (128 x 64) pre-permuted into shared in B-fragment order.
__global__ __launch_bounds__(256) void sage_mma(
    const float* __restrict__ mean, const float* __restrict__ x,
    const float* __restrict__ wl, const float* __restrict__ wr,
    const float* __restrict__ bias,
    float* __restrict__ out, __half2* __restrict__ out_h,
    int n, int relu)
{
    __shared__ uint32_t sB[16][4][32][4];   // [kc][j][lane][c], tf32 bits (32KB)
    __shared__ float sBias[64];

    int tid = threadIdx.x;

    // stage W permuted + cvt to tf32:
    // reg r = j*4+c (0..15), nt = r>>1, s = r&1; thread (t = lane&3, g = lane>>2)
    // value = W[kc*8 + t + s*4][nt*8 + g]
    for (int idx = tid; idx < 16 * 4 * 32 * 4; idx += 256) {
        int kc   = idx >> 9;
        int j    = (idx >> 7) & 3;
        int lane = (idx >> 2) & 31;
        int c    = idx & 3;
        int r  = j * 4 + c;
        int nt = r >> 1, s = r & 1;
        int t  = lane & 3, g = lane >> 2;
        int wrow = kc * 8 + t + s * 4;     // 0..127
        int wcol = nt * 8 + g;
        float v = (wrow < 64) ? wl[wrow * 64 + wcol] : wr[(wrow - 64) * 64 + wcol];
        sB[kc][j][lane][c] = f2tf32(v);
    }
    if (tid < 64) sBias[tid] = bias[tid];
    __syncthreads();

    int warp = tid >> 5, lane = tid & 31;
    int t = lane & 3, g = lane >> 2;
    int row0 = blockIdx.x * 128 + warp * 16;
    int ra = row0 + g, rb = row0 + 8 + g;
    bool va = ra < n, vb = rb < n;
    size_t raL = (size_t)(va ? ra : 0);
    size_t rbL = (size_t)(vb ? rb : 0);

    float c_[8][4];
    #pragma unroll
    for (int nt = 0; nt < 8; nt++) {
        float b0 = sBias[nt * 8 + 2 * t];
        float b1 = sBias[nt * 8 + 2 * t + 1];
        c_[nt][0] = b0; c_[nt][1] = b1; c_[nt][2] = b0; c_[nt][3] = b1;
    }

    #pragma unroll
    for (int kc = 0; kc < 16; kc++) {
        const float* __restrict__ A = (kc < 8) ? mean : x;
        int col = (kc & 7) * 8 + t;
        uint32_t a0 = f2tf32(__ldg(&A[raL * 64 + col]));
        uint32_t a1 = f2tf32(__ldg(&A[rbL * 64 + col]));
        uint32_t a2 = f2tf32(__ldg(&A[raL * 64 + col + 4]));
        uint32_t a3 = f2tf32(__ldg(&A[rbL * 64 + col + 4]));

        uint4 B0 = *(const uint4*)&sB[kc][0][lane][0];
        uint4 B1 = *(const uint4*)&sB[kc][1][lane][0];
        uint4 B2 = *(const uint4*)&sB[kc][2][lane][0];
        uint4 B3 = *(const uint4*)&sB[kc][3][lane][0];

        mma8(c_[0], a0, a1, a2, a3, B0.x, B0.y);
        mma8(c_[1], a0, a1, a2, a3, B0.z, B0.w);
        mma8(c_[2], a0, a1, a2, a3, B1.x, B1.y);
        mma8(c_[3], a0, a1, a2, a3, B1.z, B1.w);
        mma8(c_[4], a0, a1, a2, a3, B2.x, B2.y);
        mma8(c_[5], a0, a1, a2, a3, B2.z, B2.w);
        mma8(c_[6], a0, a1, a2, a3, B3.x, B3.y);
        mma8(c_[7], a0, a1, a2, a3, B3.z, B3.w);
    }

    #pragma unroll
    for (int nt = 0; nt < 8; nt++) {
        float c0 = c_[nt][0], c1 = c_[nt][1], c2 = c_[nt][2], c3 = c_[nt][3];
        if (relu) {
            c0 = fmaxf(c0, 0.f); c1 = fmaxf(c1, 0.f);
            c2 = fmaxf(c2, 0.f); c3 = fmaxf(c3, 0.f);
        }
        int col = nt * 8 + 2 * t;
        if (va) {
            *(float2*)&out[(size_t)ra * 64 + col] = make_float2(c0, c1);
            if (out_h) out_h[(size_t)ra * 32 + nt * 4 + t] = __floats2half2_rn(c0, c1);
        }
        if (vb) {
            *(float2*)&out[(size_t)rb * 64 + col] = make_float2(c2, c3);
            if (out_h) out_h[(size_t)rb * 32 + nt * 4 + t] = __floats2half2_rn(c2, c3);
        }
    }
}

// -------- label-edge dot product --------
__global__ __launch_bounds__(256) void dot_kernel(
    const float* __restrict__ hg2, const float* __restrict__ hd2,
    const int* __restrict__ ls, const int* __restrict__ ld,
    float* __restrict__ out, int nl)
{
    int t = blockIdx.x * blockDim.x + threadIdx.x;
    int e = t >> 3;
    if (e >= nl) return;
    int lane = t & 7;
    int a = ls[e];
    int b = ld[e];
    const float4* pg = (const float4*)(hg2 + (size_t)a * H);
    const float4* pd = (const float4*)(hd2 + (size_t)b * H);

    float4 g0 = pg[lane], d0 = pd[lane];
    float4 g1 = pg[lane + 8], d1 = pd[lane + 8];
    float acc = g0.x * d0.x + g0.y * d0.y + g0.z * d0.z + g0.w * d0.w
              + g1.x * d1.x + g1.y * d1.y + g1.z * d1.z + g1.w * d1.w;

    acc += __shfl_down_sync(0xFFFFFFFFu, acc, 4);
    acc += __shfl_down_sync(0xFFFFFFFFu, acc, 2);
    acc += __shfl_down_sync(0xFFFFFFFFu, acc, 1);
    if (lane == 0) out[e] = acc;
}

extern "C" void kernel_launch(void* const* d_in, const int* in_sizes, int n_in,
                              void* d_out, int out_size)
{
    const float* gene = nullptr;
    const float* dis  = nullptr;
    const float* w[8] = {};
    const float* b[4] = {};
    const int*   edge[2] = {};
    const int*   lab[2]  = {};
    int wi = 0, bi = 0, ei = 0, li = 0;
    int ne = 0, nl = 0;

    for (int i = 0; i < n_in; i++) {
        int sz = in_sizes[i];
        if (sz == NGn * H)          gene = (const float*)d_in[i];
        else if (sz == NDn * H)     dis  = (const float*)d_in[i];
        else if (sz == H * H)       { if (wi < 8) w[wi++] = (const float*)d_in[i]; }
        else if (sz == H)           { if (bi < 4) b[bi++] = (const float*)d_in[i]; }
        else if (sz == 1500000)     { if (ei < 2) { edge[ei++] = (const int*)d_in[i]; ne = sz; } }
        else if (sz == 500000)      { if (li < 2) { lab[li++]  = (const int*)d_in[i]; nl = sz; } }
    }

    int *deg, *incl, *off, *cur, *part, *adj;
    float *mG, *mD, *hg, *hd, *hg2, *hd2;
    __half2 *geneH, *disH, *hgH, *hdH;
    cudaGetSymbolAddress((void**)&deg,   g_deg);
    cudaGetSymbolAddress((void**)&incl,  g_incl);
    cudaGetSymbolAddress((void**)&off,   g_off);
    cudaGetSymbolAddress((void**)&cur,   g_cur);
    cudaGetSymbolAddress((void**)&part,  g_part);
    cudaGetSymbolAddress((void**)&adj,   g_adj);
    cudaGetSymbolAddress((void**)&mG,    g_meanG);
    cudaGetSymbolAddress((void**)&mD,    g_meanD);
    cudaGetSymbolAddress((void**)&hg,    g_hg);
    cudaGetSymbolAddress((void**)&hd,    g_hd);
    cudaGetSymbolAddress((void**)&hg2,   g_hg2);
    cudaGetSymbolAddress((void**)&hd2,   g_hd2);
    cudaGetSymbolAddress((void**)&geneH, g_geneH);
    cudaGetSymbolAddress((void**)&disH,  g_disH);
    cudaGetSymbolAddress((void**)&hgH,   g_hgH);
    cudaGetSymbolAddress((void**)&hdH,   g_hdH);

    int egrid = (ne + 255) / 256;
    int ggrid = (Mn * 32 + 255) / 256;

    // ---- CSR build ----
    zero_i4<<<(Mn / 4 + 255) / 256, 256>>>((int4*)deg, Mn / 4);
    hist_kernel<<<egrid, 256>>>(edge[0], edge[1], deg, ne);
    scan1<<<NBLK, 1024>>>(deg, incl, part, Mn);
    scan2<<<1, 128>>>(part, NBLK);
    scan3<<<(Mn + 255) / 256, 256>>>(incl, deg, part, off, cur, Mn);
    scatter_kernel<<<egrid, 256>>>(edge[0], edge[1], cur, adj, ne);

    // ---- fp16 copies of input embeddings ----
    f2h_kernel<<<(NGn * 32 + 255) / 256, 256>>>((const float2*)gene, geneH, NGn * 32);
    f2h_kernel<<<(NDn * 32 + 255) / 256, 256>>>((const float2*)dis,  disH,  NDn * 32);

    // ---- layer 1 ----
    gather_h<<<ggrid, 256>>>(geneH, disH, off, adj, (float2*)mG, (float2*)mD);
    sage_mma<<<(NDn + 127) / 128, 256>>>(mD, dis,  w[0], w[1], b[0], hd, hdH, NDn, 1);
    sage_mma<<<(NGn + 127) / 128, 256>>>(mG, gene, w[2], w[3], b[1], hg, hgH, NGn, 1);

    // ---- layer 2 ----
    gather_h<<<ggrid, 256>>>(hgH, hdH, off, adj, (float2*)mG, (float2*)mD);
    sage_mma<<<(NDn + 127) / 128, 256>>>(mD, hd, w[4], w[5], b[2], hd2, nullptr, NDn, 0);
    sage_mma<<<(NGn + 127) / 128, 256>>>(mG, hg, w[6], w[7], b[3], hg2, nullptr, NGn, 0);

    // ---- classifier ----
    int dot_grid = (nl * 8 + 255) / 256;
    dot_kernel<<<dot_grid, 256>>>(hg2, hd2, lab[0], lab[1], (float*)d_out, nl);
}

// round 4
// speedup vs baseline: 1.9280x; 1.0334x over previous
#include <cuda_runtime.h>
#include <cuda_fp16.h>
#include <cstddef>
#include <cstdint>

#define H 64
#define NGn 100000
#define NDn 30000
#define Mn (NGn + NDn)
#define NEmax 1500000
#define SCAN_B 1024
#define NBLK ((Mn + SCAN_B - 1) / SCAN_B)   // 127

// -------- scratch --------
__device__ int   g_deg [Mn];
__device__ int   g_incl[Mn];
__device__ int   g_off [Mn + 1];
__device__ int   g_cur [Mn];
__device__ int   g_part[256];
__device__ int   g_adj [2 * NEmax];
__device__ float g_meanG[(size_t)NGn * H];
__device__ float g_meanD[(size_t)NDn * H];
__device__ float g_hg [(size_t)NGn * H];
__device__ float g_hd [(size_t)NDn * H];
__device__ float g_hg2[(size_t)NGn * H];
__device__ float g_hd2[(size_t)NDn * H];
__device__ __half2 g_geneH[(size_t)NGn * 32];
__device__ __half2 g_disH [(size_t)NDn * 32];
__device__ __half2 g_hgH  [(size_t)NGn * 32];
__device__ __half2 g_hdH  [(size_t)NDn * 32];

// -------- helpers --------
__device__ __forceinline__ uint32_t f2tf32(float f) {
    uint32_t u;
    asm("cvt.rna.tf32.f32 %0, %1;" : "=r"(u) : "f"(f));
    return u;
}
__device__ __forceinline__ void mma8(float c[4],
                                     uint32_t a0, uint32_t a1, uint32_t a2, uint32_t a3,
                                     uint32_t b0, uint32_t b1) {
    asm volatile(
        "mma.sync.aligned.m16n8k8.row.col.f32.tf32.tf32.f32 "
        "{%0,%1,%2,%3},{%4,%5,%6,%7},{%8,%9},{%0,%1,%2,%3};"
        : "+f"(c[0]), "+f"(c[1]), "+f"(c[2]), "+f"(c[3])
        : "r"(a0), "r"(a1), "r"(a2), "r"(a3), "r"(b0), "r"(b1));
}

// -------- fused prologue: zero deg + fp32->fp16 of both embedding tables --------
#define NZ4   (Mn / 4)                 // 32500 int4 zeros
#define NG2   (NGn * 32)               // 3.2M half2 conversions
#define ND2   (NDn * 32)               // 960K half2 conversions
__global__ __launch_bounds__(256) void prep_kernel(
    int4* __restrict__ deg4,
    const float2* __restrict__ gene, __half2* __restrict__ geneH,
    const float2* __restrict__ dis,  __half2* __restrict__ disH)
{
    int i = blockIdx.x * blockDim.x + threadIdx.x;
    if (i < NZ4) {
        deg4[i] = make_int4(0, 0, 0, 0);
    } else if (i < NZ4 + NG2) {
        int j = i - NZ4;
        float2 v = gene[j];
        geneH[j] = __floats2half2_rn(v.x, v.y);
    } else if (i < NZ4 + NG2 + ND2) {
        int j = i - NZ4 - NG2;
        float2 v = dis[j];
        disH[j] = __floats2half2_rn(v.x, v.y);
    }
}

// -------- CSR build --------
__global__ void hist_kernel(const int* __restrict__ src, const int* __restrict__ dst,
                            int* __restrict__ deg, int ne) {
    int e = blockIdx.x * blockDim.x + threadIdx.x;
    if (e >= ne) return;
    atomicAdd(&deg[src[e]], 1);
    atomicAdd(&deg[NGn + dst[e]], 1);
}

__global__ __launch_bounds__(1024) void scan1(const int* __restrict__ deg,
                                              int* __restrict__ incl,
                                              int* __restrict__ part, int n) {
    __shared__ int ws[32];
    int i = blockIdx.x * SCAN_B + threadIdx.x;
    int v = (i < n) ? deg[i] : 0;
    int x = v;
    #pragma unroll
    for (int o = 1; o < 32; o <<= 1) {
        int y = __shfl_up_sync(0xFFFFFFFFu, x, o);
        if ((threadIdx.x & 31) >= o) x += y;
    }
    if ((threadIdx.x & 31) == 31) ws[threadIdx.x >> 5] = x;
    __syncthreads();
    if (threadIdx.x < 32) {
        int y = ws[threadIdx.x];
        #pragma unroll
        for (int o = 1; o < 32; o <<= 1) {
            int z = __shfl_up_sync(0xFFFFFFFFu, y, o);
            if (threadIdx.x >= o) y += z;
        }
        ws[threadIdx.x] = y;
    }
    __syncthreads();
    if (threadIdx.x >= 32) x += ws[(threadIdx.x >> 5) - 1];
    if (i < n) incl[i] = x;
    if (threadIdx.x == 1023) part[blockIdx.x] = x;
}

// fused scan2+scan3: every block exclusive-scans the 127 partials itself,
// then finalizes off[] and cur[] for its 1024 nodes.
__global__ __launch_bounds__(1024) void scan23(
    const int* __restrict__ incl, const int* __restrict__ deg,
    const int* __restrict__ part,
    int* __restrict__ off, int* __restrict__ cur, int n)
{
    __shared__ int sp[128];
    __shared__ int ws[4];
    int t = threadIdx.x;
    int x = 0, v = 0;
    if (t < 128) {
        v = (t < NBLK) ? part[t] : 0;
        x = v;
        #pragma unroll
        for (int o = 1; o < 32; o <<= 1) {
            int y = __shfl_up_sync(0xFFFFFFFFu, x, o);
            if ((t & 31) >= o) x += y;
        }
        if ((t & 31) == 31) ws[t >> 5] = x;
    }
    __syncthreads();
    if (t < 128) {
        int add = 0;
        for (int w = 0; w < (t >> 5); w++) add += ws[w];
        sp[t] = x + add - v;    // exclusive prefix of block partials
    }
    __syncthreads();
    int i = blockIdx.x * SCAN_B + t;
    if (i < n) {
        int inc = incl[i] + sp[blockIdx.x];
        off[i + 1] = inc;
        cur[i] = inc - deg[i];
        if (i == 0) off[0] = 0;
    }
}

__global__ void scatter_kernel(const int* __restrict__ src, const int* __restrict__ dst,
                               int* __restrict__ cur, int* __restrict__ adj, int ne) {
    int e = blockIdx.x * blockDim.x + threadIdx.x;
    if (e >= ne) return;
    int s = src[e], d = dst[e];
    int p = atomicAdd(&cur[s], 1);        adj[p] = d;
    int q = atomicAdd(&cur[NGn + d], 1);  adj[q] = s;
}

// -------- warp-per-node gather-mean, fp16 input, fp32 accum, 8-deep unroll --------
__global__ __launch_bounds__(256) void gather_h(
    const __half2* __restrict__ xg, const __half2* __restrict__ xd,
    const int* __restrict__ off, const int* __restrict__ adj,
    float2* __restrict__ outG, float2* __restrict__ outD)
{
    int w = (blockIdx.x * blockDim.x + threadIdx.x) >> 5;
    if (w >= Mn) return;
    int lane = threadIdx.x & 31;
    int beg = off[w], end = off[w + 1];
    const __half2* __restrict__ x = (w < NGn) ? xd : xg;

    float2 a0 = {0.f, 0.f}, a1 = {0.f, 0.f}, a2 = {0.f, 0.f}, a3 = {0.f, 0.f};
    int j = beg;
    for (; j + 8 <= end; j += 8) {
        int n0 = __ldg(&adj[j + 0]);
        int n1 = __ldg(&adj[j + 1]);
        int n2 = __ldg(&adj[j + 2]);
        int n3 = __ldg(&adj[j + 3]);
        int n4 = __ldg(&adj[j + 4]);
        int n5 = __ldg(&adj[j + 5]);
        int n6 = __ldg(&adj[j + 6]);
        int n7 = __ldg(&adj[j + 7]);
        float2 v0 = __half22float2(x[(size_t)n0 * 32 + lane]);
        float2 v1 = __half22float2(x[(size_t)n1 * 32 + lane]);
        float2 v2 = __half22float2(x[(size_t)n2 * 32 + lane]);
        float2 v3 = __half22float2(x[(size_t)n3 * 32 + lane]);
        float2 v4 = __half22float2(x[(size_t)n4 * 32 + lane]);
        float2 v5 = __half22float2(x[(size_t)n5 * 32 + lane]);
        float2 v6 = __half22float2(x[(size_t)n6 * 32 + lane]);
        float2 v7 = __half22float2(x[(size_t)n7 * 32 + lane]);
        a0.x += v0.x + v4.x; a0.y += v0.y + v4.y;
        a1.x += v1.x + v5.x; a1.y += v1.y + v5.y;
        a2.x += v2.x + v6.x; a2.y += v2.y + v6.y;
        a3.x += v3.x + v7.x; a3.y += v3.y + v7.y;
    }
    for (; j + 4 <= end; j += 4) {
        int n0 = __ldg(&adj[j + 0]);
        int n1 = __ldg(&adj[j + 1]);
        int n2 = __ldg(&adj[j + 2]);
        int n3 = __ldg(&adj[j + 3]);
        float2 v0 = __half22float2(x[(size_t)n0 * 32 + lane]);
        float2 v1 = __half22float2(x[(size_t)n1 * 32 + lane]);
        float2 v2 = __half22float2(x[(size_t)n2 * 32 + lane]);
        float2 v3 = __half22float2(x[(size_t)n3 * 32 + lane]);
        a0.x += v0.x; a0.y += v0.y;
        a1.x += v1.x; a1.y += v1.y;
        a2.x += v2.x; a2.y += v2.y;
        a3.x += v3.x; a3.y += v3.y;
    }
    for (; j < end; j++) {
        int nn = __ldg(&adj[j]);
        float2 v = __half22float2(x[(size_t)nn * 32 + lane]);
        a0.x += v.x; a0.y += v.y;
    }
    float2 s;
    s.x = (a0.x + a1.x) + (a2.x + a3.x);
    s.y = (a0.y + a1.y) + (a2.y + a3.y);
    float inv = 1.0f / fmaxf((float)(end - beg), 1.0f);
    s.x *= inv; s.y *= inv;
    if (w < NGn) outG[(size_t)w * 32 + lane] = s;
    else         outD[(size_t)(w - NGn) * 32 + lane] = s;
}

// -------- fused per-layer SAGE linear via tf32 mma.sync --------
// Blocks [0, nbD) process the disease matrix; blocks [nbD, nbD+nbG) the gene matrix.
__global__ __launch_bounds__(256) void sage_mma2(
    const float* __restrict__ mD, const float* __restrict__ xD,
    const float* __restrict__ wDl, const float* __restrict__ wDr,
    const float* __restrict__ bDp,
    float* __restrict__ outD, __half2* __restrict__ outDh, int nD,
    const float* __restrict__ mG, const float* __restrict__ xG,
    const float* __restrict__ wGl, const float* __restrict__ wGr,
    const float* __restrict__ bGp,
    float* __restrict__ outG, __half2* __restrict__ outGh, int nG,
    int relu)
{
    __shared__ uint32_t sB[16][4][32][4];   // 32KB permuted tf32 W = [wl; wr]
    __shared__ float sBias[64];

    int nbD = (nD + 127) / 128;
    bool isD = ((int)blockIdx.x < nbD);
    const float* mean = isD ? mD : mG;
    const float* x    = isD ? xD : xG;
    const float* wl   = isD ? wDl : wGl;
    const float* wr   = isD ? wDr : wGr;
    const float* bias = isD ? bDp : bGp;
    float* out        = isD ? outD : outG;
    __half2* out_h    = isD ? outDh : outGh;
    int n             = isD ? nD : nG;
    int blk           = isD ? blockIdx.x : (blockIdx.x - nbD);

    int tid = threadIdx.x;

    for (int idx = tid; idx < 16 * 4 * 32 * 4; idx += 256) {
        int kc   = idx >> 9;
        int j    = (idx >> 7) & 3;
        int lane = (idx >> 2) & 31;
        int c    = idx & 3;
        int r  = j * 4 + c;
        int nt = r >> 1, s = r & 1;
        int t  = lane & 3, g = lane >> 2;
        int wrow = kc * 8 + t + s * 4;
        int wcol = nt * 8 + g;
        float v = (wrow < 64) ? wl[wrow * 64 + wcol] : wr[(wrow - 64) * 64 + wcol];
        sB[kc][j][lane][c] = f2tf32(v);
    }
    if (tid < 64) sBias[tid] = bias[tid];
    __syncthreads();

    int warp = tid >> 5, lane = tid & 31;
    int t = lane & 3, g = lane >> 2;
    int row0 = blk * 128 + warp * 16;
    int ra = row0 + g, rb = row0 + 8 + g;
    bool va = ra < n, vb = rb < n;
    size_t raL = (size_t)(va ? ra : 0);
    size_t rbL = (size_t)(vb ? rb : 0);

    float c_[8][4];
    #pragma unroll
    for (int nt = 0; nt < 8; nt++) {
        float b0 = sBias[nt * 8 + 2 * t];
        float b1 = sBias[nt * 8 + 2 * t + 1];
        c_[nt][0] = b0; c_[nt][1] = b1; c_[nt][2] = b0; c_[nt][3] = b1;
    }

    #pragma unroll
    for (int kc = 0; kc < 16; kc++) {
        const float* __restrict__ A = (kc < 8) ? mean : x;
        int col = (kc & 7) * 8 + t;
        uint32_t a0 = f2tf32(__ldg(&A[raL * 64 + col]));
        uint32_t a1 = f2tf32(__ldg(&A[rbL * 64 + col]));
        uint32_t a2 = f2tf32(__ldg(&A[raL * 64 + col + 4]));
        uint32_t a3 = f2tf32(__ldg(&A[rbL * 64 + col + 4]));

        uint4 B0 = *(const uint4*)&sB[kc][0][lane][0];
        uint4 B1 = *(const uint4*)&sB[kc][1][lane][0];
        uint4 B2 = *(const uint4*)&sB[kc][2][lane][0];
        uint4 B3 = *(const uint4*)&sB[kc][3][lane][0];

        mma8(c_[0], a0, a1, a2, a3, B0.x, B0.y);
        mma8(c_[1], a0, a1, a2, a3, B0.z, B0.w);
        mma8(c_[2], a0, a1, a2, a3, B1.x, B1.y);
        mma8(c_[3], a0, a1, a2, a3, B1.z, B1.w);
        mma8(c_[4], a0, a1, a2, a3, B2.x, B2.y);
        mma8(c_[5], a0, a1, a2, a3, B2.z, B2.w);
        mma8(c_[6], a0, a1, a2, a3, B3.x, B3.y);
        mma8(c_[7], a0, a1, a2, a3, B3.z, B3.w);
    }

    #pragma unroll
    for (int nt = 0; nt < 8; nt++) {
        float c0 = c_[nt][0], c1 = c_[nt][1], c2 = c_[nt][2], c3 = c_[nt][3];
        if (relu) {
            c0 = fmaxf(c0, 0.f); c1 = fmaxf(c1, 0.f);
            c2 = fmaxf(c2, 0.f); c3 = fmaxf(c3, 0.f);
        }
        int col = nt * 8 + 2 * t;
        if (va) {
            *(float2*)&out[(size_t)ra * 64 + col] = make_float2(c0, c1);
            if (out_h) out_h[(size_t)ra * 32 + nt * 4 + t] = __floats2half2_rn(c0, c1);
        }
        if (vb) {
            *(float2*)&out[(size_t)rb * 64 + col] = make_float2(c2, c3);
            if (out_h) out_h[(size_t)rb * 32 + nt * 4 + t] = __floats2half2_rn(c2, c3);
        }
    }
}

// -------- label-edge dot product --------
__global__ __launch_bounds__(256) void dot_kernel(
    const float* __restrict__ hg2, const float* __restrict__ hd2,
    const int* __restrict__ ls, const int* __restrict__ ld,
    float* __restrict__ out, int nl)
{
    int t = blockIdx.x * blockDim.x + threadIdx.x;
    int e = t >> 3;
    if (e >= nl) return;
    int lane = t & 7;
    int a = ls[e];
    int b = ld[e];
    const float4* pg = (const float4*)(hg2 + (size_t)a * H);
    const float4* pd = (const float4*)(hd2 + (size_t)b * H);

    float4 g0 = pg[lane], d0 = pd[lane];
    float4 g1 = pg[lane + 8], d1 = pd[lane + 8];
    float acc = g0.x * d0.x + g0.y * d0.y + g0.z * d0.z + g0.w * d0.w
              + g1.x * d1.x + g1.y * d1.y + g1.z * d1.z + g1.w * d1.w;

    acc += __shfl_down_sync(0xFFFFFFFFu, acc, 4);
    acc += __shfl_down_sync(0xFFFFFFFFu, acc, 2);
    acc += __shfl_down_sync(0xFFFFFFFFu, acc, 1);
    if (lane == 0) out[e] = acc;
}

extern "C" void kernel_launch(void* const* d_in, const int* in_sizes, int n_in,
                              void* d_out, int out_size)
{
    const float* gene = nullptr;
    const float* dis  = nullptr;
    const float* w[8] = {};
    const float* b[4] = {};
    const int*   edge[2] = {};
    const int*   lab[2]  = {};
    int wi = 0, bi = 0, ei = 0, li = 0;
    int ne = 0, nl = 0;

    for (int i = 0; i < n_in; i++) {
        int sz = in_sizes[i];
        if (sz == NGn * H)          gene = (const float*)d_in[i];
        else if (sz == NDn * H)     dis  = (const float*)d_in[i];
        else if (sz == H * H)       { if (wi < 8) w[wi++] = (const float*)d_in[i]; }
        else if (sz == H)           { if (bi < 4) b[bi++] = (const float*)d_in[i]; }
        else if (sz == 1500000)     { if (ei < 2) { edge[ei++] = (const int*)d_in[i]; ne = sz; } }
        else if (sz == 500000)      { if (li < 2) { lab[li++]  = (const int*)d_in[i]; nl = sz; } }
    }

    int *deg, *incl, *off, *cur, *part, *adj;
    float *mG, *mD, *hg, *hd, *hg2, *hd2;
    __half2 *geneH, *disH, *hgH, *hdH;
    cudaGetSymbolAddress((void**)&deg,   g_deg);
    cudaGetSymbolAddress((void**)&incl,  g_incl);
    cudaGetSymbolAddress((void**)&off,   g_off);
    cudaGetSymbolAddress((void**)&cur,   g_cur);
    cudaGetSymbolAddress((void**)&part,  g_part);
    cudaGetSymbolAddress((void**)&adj,   g_adj);
    cudaGetSymbolAddress((void**)&mG,    g_meanG);
    cudaGetSymbolAddress((void**)&mD,    g_meanD);
    cudaGetSymbolAddress((void**)&hg,    g_hg);
    cudaGetSymbolAddress((void**)&hd,    g_hd);
    cudaGetSymbolAddress((void**)&hg2,   g_hg2);
    cudaGetSymbolAddress((void**)&hd2,   g_hd2);
    cudaGetSymbolAddress((void**)&geneH, g_geneH);
    cudaGetSymbolAddress((void**)&disH,  g_disH);
    cudaGetSymbolAddress((void**)&hgH,   g_hgH);
    cudaGetSymbolAddress((void**)&hdH,   g_hdH);

    int egrid = (ne + 255) / 256;
    int ggrid = (Mn * 32 + 255) / 256;
    int prep_items = NZ4 + NG2 + ND2;
    int lin_grid = (NDn + 127) / 128 + (NGn + 127) / 128;

    // ---- prologue + CSR build (5 launches) ----
    prep_kernel<<<(prep_items + 255) / 256, 256>>>(
        (int4*)deg, (const float2*)gene, geneH, (const float2*)dis, disH);
    hist_kernel<<<egrid, 256>>>(edge[0], edge[1], deg, ne);
    scan1<<<NBLK, 1024>>>(deg, incl, part, Mn);
    scan23<<<NBLK, 1024>>>(incl, deg, part, off, cur, Mn);
    scatter_kernel<<<egrid, 256>>>(edge[0], edge[1], cur, adj, ne);

    // ---- layer 1 ----
    gather_h<<<ggrid, 256>>>(geneH, disH, off, adj, (float2*)mG, (float2*)mD);
    sage_mma2<<<lin_grid, 256>>>(mD, dis,  w[0], w[1], b[0], hd, hdH, NDn,
                                 mG, gene, w[2], w[3], b[1], hg, hgH, NGn, 1);

    // ---- layer 2 ----
    gather_h<<<ggrid, 256>>>(hgH, hdH, off, adj, (float2*)mG, (float2*)mD);
    sage_mma2<<<lin_grid, 256>>>(mD, hd, w[4], w[5], b[2], hd2, nullptr, NDn,
                                 mG, hg, w[6], w[7], b[3], hg2, nullptr, NGn, 0);

    // ---- classifier ----
    int dot_grid = (nl * 8 + 255) / 256;
    dot_kernel<<<dot_grid, 256>>>(hg2, hd2, lab[0], lab[1], (float*)d_out, nl);
}

// round 5
// speedup vs baseline: 2.1344x; 1.1070x over previous
#include <cuda_runtime.h>
#include <cuda_fp16.h>
#include <cstddef>
#include <cstdint>

#define H 64
#define NGn 100000
#define NDn 30000
#define Mn (NGn + NDn)
#define NEmax 1500000
#define SCAN_B 1024
#define NBLK ((Mn + SCAN_B - 1) / SCAN_B)   // 127

// -------- scratch --------
__device__ int   g_deg [Mn];
__device__ int   g_incl[Mn];
__device__ int   g_off [Mn + 1];
__device__ int   g_cur [Mn];
__device__ int   g_part[256];
__device__ __align__(16) int g_adj [2 * NEmax];
__device__ float g_hg2[(size_t)NGn * H];
__device__ float g_hd2[(size_t)NDn * H];
__device__ __half2 g_geneH[(size_t)NGn * 32];
__device__ __half2 g_disH [(size_t)NDn * 32];
__device__ __half2 g_hgH  [(size_t)NGn * 32];
__device__ __half2 g_hdH  [(size_t)NDn * 32];
__device__ __half2 g_mGH  [(size_t)NGn * 32];
__device__ __half2 g_mDH  [(size_t)NDn * 32];

// -------- helpers --------
__device__ __forceinline__ uint32_t packh2(float a, float b) {
    __half2 h = __floats2half2_rn(a, b);
    return *reinterpret_cast<uint32_t*>(&h);
}
__device__ __forceinline__ void mma16(float c[4],
                                      uint32_t a0, uint32_t a1, uint32_t a2, uint32_t a3,
                                      uint32_t b0, uint32_t b1) {
    asm volatile(
        "mma.sync.aligned.m16n8k16.row.col.f32.f16.f16.f32 "
        "{%0,%1,%2,%3},{%4,%5,%6,%7},{%8,%9},{%0,%1,%2,%3};"
        : "+f"(c[0]), "+f"(c[1]), "+f"(c[2]), "+f"(c[3])
        : "r"(a0), "r"(a1), "r"(a2), "r"(a3), "r"(b0), "r"(b1));
}

// -------- fused prologue: zero deg + fp32->fp16 of both embedding tables --------
#define NZ4   (Mn / 4)
#define NG2   (NGn * 32)
#define ND2   (NDn * 32)
__global__ __launch_bounds__(256) void prep_kernel(
    int4* __restrict__ deg4,
    const float2* __restrict__ gene, __half2* __restrict__ geneH,
    const float2* __restrict__ dis,  __half2* __restrict__ disH)
{
    int i = blockIdx.x * blockDim.x + threadIdx.x;
    if (i < NZ4) {
        deg4[i] = make_int4(0, 0, 0, 0);
    } else if (i < NZ4 + NG2) {
        int j = i - NZ4;
        float2 v = gene[j];
        geneH[j] = __floats2half2_rn(v.x, v.y);
    } else if (i < NZ4 + NG2 + ND2) {
        int j = i - NZ4 - NG2;
        float2 v = dis[j];
        disH[j] = __floats2half2_rn(v.x, v.y);
    }
}

// -------- CSR build --------
__global__ void hist_kernel(const int* __restrict__ src, const int* __restrict__ dst,
                            int* __restrict__ deg, int ne) {
    int e = blockIdx.x * blockDim.x + threadIdx.x;
    if (e >= ne) return;
    atomicAdd(&deg[src[e]], 1);
    atomicAdd(&deg[NGn + dst[e]], 1);
}

__global__ __launch_bounds__(1024) void scan1(const int* __restrict__ deg,
                                              int* __restrict__ incl,
                                              int* __restrict__ part, int n) {
    __shared__ int ws[32];
    int i = blockIdx.x * SCAN_B + threadIdx.x;
    int v = (i < n) ? deg[i] : 0;
    int x = v;
    #pragma unroll
    for (int o = 1; o < 32; o <<= 1) {
        int y = __shfl_up_sync(0xFFFFFFFFu, x, o);
        if ((threadIdx.x & 31) >= o) x += y;
    }
    if ((threadIdx.x & 31) == 31) ws[threadIdx.x >> 5] = x;
    __syncthreads();
    if (threadIdx.x < 32) {
        int y = ws[threadIdx.x];
        #pragma unroll
        for (int o = 1; o < 32; o <<= 1) {
            int z = __shfl_up_sync(0xFFFFFFFFu, y, o);
            if (threadIdx.x >= o) y += z;
        }
        ws[threadIdx.x] = y;
    }
    __syncthreads();
    if (threadIdx.x >= 32) x += ws[(threadIdx.x >> 5) - 1];
    if (i < n) incl[i] = x;
    if (threadIdx.x == 1023) part[blockIdx.x] = x;
}

__global__ __launch_bounds__(1024) void scan23(
    const int* __restrict__ incl, const int* __restrict__ deg,
    const int* __restrict__ part,
    int* __restrict__ off, int* __restrict__ cur, int n)
{
    __shared__ int sp[128];
    __shared__ int ws[4];
    int t = threadIdx.x;
    int x = 0, v = 0;
    if (t < 128) {
        v = (t < NBLK) ? part[t] : 0;
        x = v;
        #pragma unroll
        for (int o = 1; o < 32; o <<= 1) {
            int y = __shfl_up_sync(0xFFFFFFFFu, x, o);
            if ((t & 31) >= o) x += y;
        }
        if ((t & 31) == 31) ws[t >> 5] = x;
    }
    __syncthreads();
    if (t < 128) {
        int add = 0;
        for (int w = 0; w < (t >> 5); w++) add += ws[w];
        sp[t] = x + add - v;
    }
    __syncthreads();
    int i = blockIdx.x * SCAN_B + t;
    if (i < n) {
        int inc = incl[i] + sp[blockIdx.x];
        off[i + 1] = inc;
        cur[i] = inc - deg[i];
        if (i == 0) off[0] = 0;
    }
}

__global__ void scatter_kernel(const int* __restrict__ src, const int* __restrict__ dst,
                               int* __restrict__ cur, int* __restrict__ adj, int ne) {
    int e = blockIdx.x * blockDim.x + threadIdx.x;
    if (e >= ne) return;
    int s = src[e], d = dst[e];
    int p = atomicAdd(&cur[s], 1);        adj[p] = d;
    int q = atomicAdd(&cur[NGn + d], 1);  adj[q] = s;
}

// -------- warp-per-node gather-mean, fp16 in/out, fp32 accum, int4 adj --------
__global__ __launch_bounds__(256) void gather_h(
    const __half2* __restrict__ xg, const __half2* __restrict__ xd,
    const int* __restrict__ off, const int* __restrict__ adj,
    __half2* __restrict__ outG, __half2* __restrict__ outD)
{
    int w = (blockIdx.x * blockDim.x + threadIdx.x) >> 5;
    if (w >= Mn) return;
    int lane = threadIdx.x & 31;
    int beg = off[w], end = off[w + 1];
    const __half2* __restrict__ x = (w < NGn) ? xd : xg;
    const int4* __restrict__ adj4 = (const int4*)adj;

    float2 a0 = {0.f, 0.f}, a1 = {0.f, 0.f}, a2 = {0.f, 0.f}, a3 = {0.f, 0.f};
    int j = beg;
    // peel to 16B alignment
    int aligned = (beg + 3) & ~3;
    int pre = (aligned < end) ? aligned : end;
    for (; j < pre; j++) {
        int nn = __ldg(&adj[j]);
        float2 v = __half22float2(x[(size_t)nn * 32 + lane]);
        a0.x += v.x; a0.y += v.y;
    }
    for (; j + 8 <= end; j += 8) {
        int4 q0 = __ldg(&adj4[j >> 2]);
        int4 q1 = __ldg(&adj4[(j >> 2) + 1]);
        float2 v0 = __half22float2(x[(size_t)q0.x * 32 + lane]);
        float2 v1 = __half22float2(x[(size_t)q0.y * 32 + lane]);
        float2 v2 = __half22float2(x[(size_t)q0.z * 32 + lane]);
        float2 v3 = __half22float2(x[(size_t)q0.w * 32 + lane]);
        float2 v4 = __half22float2(x[(size_t)q1.x * 32 + lane]);
        float2 v5 = __half22float2(x[(size_t)q1.y * 32 + lane]);
        float2 v6 = __half22float2(x[(size_t)q1.z * 32 + lane]);
        float2 v7 = __half22float2(x[(size_t)q1.w * 32 + lane]);
        a0.x += v0.x + v4.x; a0.y += v0.y + v4.y;
        a1.x += v1.x + v5.x; a1.y += v1.y + v5.y;
        a2.x += v2.x + v6.x; a2.y += v2.y + v6.y;
        a3.x += v3.x + v7.x; a3.y += v3.y + v7.y;
    }
    if (j + 4 <= end) {
        int4 q = __ldg(&adj4[j >> 2]);
        float2 v0 = __half22float2(x[(size_t)q.x * 32 + lane]);
        float2 v1 = __half22float2(x[(size_t)q.y * 32 + lane]);
        float2 v2 = __half22float2(x[(size_t)q.z * 32 + lane]);
        float2 v3 = __half22float2(x[(size_t)q.w * 32 + lane]);
        a0.x += v0.x; a0.y += v0.y;
        a1.x += v1.x; a1.y += v1.y;
        a2.x += v2.x; a2.y += v2.y;
        a3.x += v3.x; a3.y += v3.y;
        j += 4;
    }
    for (; j < end; j++) {
        int nn = __ldg(&adj[j]);
        float2 v = __half22float2(x[(size_t)nn * 32 + lane]);
        a0.x += v.x; a0.y += v.y;
    }
    float sx = (a0.x + a1.x) + (a2.x + a3.x);
    float sy = (a0.y + a1.y) + (a2.y + a3.y);
    float inv = 1.0f / fmaxf((float)(end - beg), 1.0f);
    __half2 r = __floats2half2_rn(sx * inv, sy * inv);
    if (w < NGn) outG[(size_t)w * 32 + lane] = r;
    else         outD[(size_t)(w - NGn) * 32 + lane] = r;
}

// -------- fused per-layer SAGE linear via fp16 mma.sync (m16n8k16) --------
// A inputs fp16 (mean ; x), B = [wl; wr] pre-packed fp16 in shared, acc fp32.
// Blocks [0, nbD): disease matrix; [nbD, nbD+nbG): gene matrix.
__global__ __launch_bounds__(256) void sage_mma2(
    const __half2* __restrict__ mDh, const __half2* __restrict__ xDh,
    const float* __restrict__ wDl, const float* __restrict__ wDr,
    const float* __restrict__ bDp,
    float* __restrict__ outD, __half2* __restrict__ outDh, int nD,
    const __half2* __restrict__ mGh, const __half2* __restrict__ xGh,
    const float* __restrict__ wGl, const float* __restrict__ wGr,
    const float* __restrict__ bGp,
    float* __restrict__ outG, __half2* __restrict__ outGh, int nG,
    int relu)
{
    __shared__ uint2 sB[8][8][32];   // [kc][nt][lane] packed half2 pairs (16KB)
    __shared__ float sBias[64];

    int nbD = (nD + 127) / 128;
    bool isD = ((int)blockIdx.x < nbD);
    const __half2* mean = isD ? mDh : mGh;
    const __half2* x    = isD ? xDh : xGh;
    const float* wl     = isD ? wDl : wGl;
    const float* wr     = isD ? wDr : wGr;
    const float* bias   = isD ? bDp : bGp;
    float* out          = isD ? outD : outG;
    __half2* out_h      = isD ? outDh : outGh;
    int n               = isD ? nD : nG;
    int blk             = isD ? blockIdx.x : (blockIdx.x - nbD);

    int tid = threadIdx.x;

    // stage W = [wl; wr] (128 x 64) in fp16 B-fragment order.
    // b0 = W[k0+2t][c], W[k0+2t+1][c];  b1 = W[k0+2t+8][c], W[k0+2t+9][c]
    for (int idx = tid; idx < 8 * 8 * 32; idx += 256) {
        int kc   = idx >> 8;
        int nt   = (idx >> 5) & 7;
        int lane = idx & 31;
        int t = lane & 3, g = lane >> 2;
        int c = nt * 8 + g;
        int k0 = kc * 16;
        int r0 = k0 + 2 * t, r2 = k0 + 2 * t + 8;
        float w00 = (r0 < 64)     ? wl[r0 * 64 + c]       : wr[(r0 - 64) * 64 + c];
        float w01 = (r0 + 1 < 64) ? wl[(r0 + 1) * 64 + c] : wr[(r0 - 63) * 64 + c];
        float w10 = (r2 < 64)     ? wl[r2 * 64 + c]       : wr[(r2 - 64) * 64 + c];
        float w11 = (r2 + 1 < 64) ? wl[(r2 + 1) * 64 + c] : wr[(r2 - 63) * 64 + c];
        sB[kc][nt][lane] = make_uint2(packh2(w00, w01), packh2(w10, w11));
    }
    if (tid < 64) sBias[tid] = bias[tid];
    __syncthreads();

    int warp = tid >> 5, lane = tid & 31;
    int t = lane & 3, g = lane >> 2;
    int row0 = blk * 128 + warp * 16;
    int ra = row0 + g, rb = row0 + 8 + g;
    bool va = ra < n, vb = rb < n;
    size_t raL = (size_t)(va ? ra : 0);
    size_t rbL = (size_t)(vb ? rb : 0);

    const uint32_t* meanU = (const uint32_t*)mean;
    const uint32_t* xU    = (const uint32_t*)x;

    float c_[8][4];
    #pragma unroll
    for (int nt = 0; nt < 8; nt++) {
        float b0 = sBias[nt * 8 + 2 * t];
        float b1 = sBias[nt * 8 + 2 * t + 1];
        c_[nt][0] = b0; c_[nt][1] = b1; c_[nt][2] = b0; c_[nt][3] = b1;
    }

    #pragma unroll
    for (int kc = 0; kc < 8; kc++) {
        const uint32_t* __restrict__ A = (kc < 4) ? meanU : xU;
        int base = (kc & 3) * 8;
        uint32_t a0 = __ldg(&A[raL * 32 + base + t]);
        uint32_t a1 = __ldg(&A[rbL * 32 + base + t]);
        uint32_t a2 = __ldg(&A[raL * 32 + base + t + 4]);
        uint32_t a3 = __ldg(&A[rbL * 32 + base + t + 4]);
        #pragma unroll
        for (int nt = 0; nt < 8; nt++) {
            uint2 B = sB[kc][nt][lane];
            mma16(c_[nt], a0, a1, a2, a3, B.x, B.y);
        }
    }

    #pragma unroll
    for (int nt = 0; nt < 8; nt++) {
        float c0 = c_[nt][0], c1 = c_[nt][1], c2 = c_[nt][2], c3 = c_[nt][3];
        if (relu) {
            c0 = fmaxf(c0, 0.f); c1 = fmaxf(c1, 0.f);
            c2 = fmaxf(c2, 0.f); c3 = fmaxf(c3, 0.f);
        }
        int col = nt * 8 + 2 * t;
        if (va) {
            if (out)   *(float2*)&out[(size_t)ra * 64 + col] = make_float2(c0, c1);
            if (out_h) out_h[(size_t)ra * 32 + nt * 4 + t] = __floats2half2_rn(c0, c1);
        }
        if (vb) {
            if (out)   *(float2*)&out[(size_t)rb * 64 + col] = make_float2(c2, c3);
            if (out_h) out_h[(size_t)rb * 32 + nt * 4 + t] = __floats2half2_rn(c2, c3);
        }
    }
}

// -------- label-edge dot product (fp32) --------
__global__ __launch_bounds__(256) void dot_kernel(
    const float* __restrict__ hg2, const float* __restrict__ hd2,
    const int* __restrict__ ls, const int* __restrict__ ld,
    float* __restrict__ out, int nl)
{
    int t = blockIdx.x * blockDim.x + threadIdx.x;
    int e = t >> 3;
    if (e >= nl) return;
    int lane = t & 7;
    int a = ls[e];
    int b = ld[e];
    const float4* pg = (const float4*)(hg2 + (size_t)a * H);
    const float4* pd = (const float4*)(hd2 + (size_t)b * H);

    float4 g0 = pg[lane], d0 = pd[lane];
    float4 g1 = pg[lane + 8], d1 = pd[lane + 8];
    float acc = g0.x * d0.x + g0.y * d0.y + g0.z * d0.z + g0.w * d0.w
              + g1.x * d1.x + g1.y * d1.y + g1.z * d1.z + g1.w * d1.w;

    acc += __shfl_down_sync(0xFFFFFFFFu, acc, 4);
    acc += __shfl_down_sync(0xFFFFFFFFu, acc, 2);
    acc += __shfl_down_sync(0xFFFFFFFFu, acc, 1);
    if (lane == 0) out[e] = acc;
}

extern "C" void kernel_launch(void* const* d_in, const int* in_sizes, int n_in,
                              void* d_out, int out_size)
{
    const float* gene = nullptr;
    const float* dis  = nullptr;
    const float* w[8] = {};
    const float* b[4] = {};
    const int*   edge[2] = {};
    const int*   lab[2]  = {};
    int wi = 0, bi = 0, ei = 0, li = 0;
    int ne = 0, nl = 0;

    for (int i = 0; i < n_in; i++) {
        int sz = in_sizes[i];
        if (sz == NGn * H)          gene = (const float*)d_in[i];
        else if (sz == NDn * H)     dis  = (const float*)d_in[i];
        else if (sz == H * H)       { if (wi < 8) w[wi++] = (const float*)d_in[i]; }
        else if (sz == H)           { if (bi < 4) b[bi++] = (const float*)d_in[i]; }
        else if (sz == 1500000)     { if (ei < 2) { edge[ei++] = (const int*)d_in[i]; ne = sz; } }
        else if (sz == 500000)      { if (li < 2) { lab[li++]  = (const int*)d_in[i]; nl = sz; } }
    }

    int *deg, *incl, *off, *cur, *part, *adj;
    float *hg2, *hd2;
    __half2 *geneH, *disH, *hgH, *hdH, *mGH, *mDH;
    cudaGetSymbolAddress((void**)&deg,   g_deg);
    cudaGetSymbolAddress((void**)&incl,  g_incl);
    cudaGetSymbolAddress((void**)&off,   g_off);
    cudaGetSymbolAddress((void**)&cur,   g_cur);
    cudaGetSymbolAddress((void**)&part,  g_part);
    cudaGetSymbolAddress((void**)&adj,   g_adj);
    cudaGetSymbolAddress((void**)&hg2,   g_hg2);
    cudaGetSymbolAddress((void**)&hd2,   g_hd2);
    cudaGetSymbolAddress((void**)&geneH, g_geneH);
    cudaGetSymbolAddress((void**)&disH,  g_disH);
    cudaGetSymbolAddress((void**)&hgH,   g_hgH);
    cudaGetSymbolAddress((void**)&hdH,   g_hdH);
    cudaGetSymbolAddress((void**)&mGH,   g_mGH);
    cudaGetSymbolAddress((void**)&mDH,   g_mDH);

    int egrid = (ne + 255) / 256;
    int ggrid = (Mn * 32 + 255) / 256;
    int prep_items = NZ4 + NG2 + ND2;
    int lin_grid = (NDn + 127) / 128 + (NGn + 127) / 128;

    // ---- prologue + CSR build ----
    prep_kernel<<<(prep_items + 255) / 256, 256>>>(
        (int4*)deg, (const float2*)gene, geneH, (const float2*)dis, disH);
    hist_kernel<<<egrid, 256>>>(edge[0], edge[1], deg, ne);
    scan1<<<NBLK, 1024>>>(deg, incl, part, Mn);
    scan23<<<NBLK, 1024>>>(incl, deg, part, off, cur, Mn);
    scatter_kernel<<<egrid, 256>>>(edge[0], edge[1], cur, adj, ne);

    // ---- layer 1 (outputs fp16 only) ----
    gather_h<<<ggrid, 256>>>(geneH, disH, off, adj, mGH, mDH);
    sage_mma2<<<lin_grid, 256>>>(mDH, disH, w[0], w[1], b[0], nullptr, hdH, NDn,
                                 mGH, geneH, w[2], w[3], b[1], nullptr, hgH, NGn, 1);

    // ---- layer 2 (outputs fp32 for classifier) ----
    gather_h<<<ggrid, 256>>>(hgH, hdH, off, adj, mGH, mDH);
    sage_mma2<<<lin_grid, 256>>>(mDH, hdH, w[4], w[5], b[2], hd2, nullptr, NDn,
                                 mGH, hgH, w[6], w[7], b[3], hg2, nullptr, NGn, 0);

    // ---- classifier ----
    int dot_grid = (nl * 8 + 255) / 256;
    dot_kernel<<<dot_grid, 256>>>(hg2, hd2, lab[0], lab[1], (float*)d_out, nl);
}

// round 6
// speedup vs baseline: 2.1934x; 1.0277x over previous
#include <cuda_runtime.h>
#include <cuda_fp16.h>
#include <cstddef>
#include <cstdint>

#define H 64
#define NGn 100000
#define NDn 30000
#define Mn (NGn + NDn)
#define NEmax 1500000
#define SCAN_B 1024
#define NBLK ((Mn + SCAN_B - 1) / SCAN_B)   // 127

// -------- scratch --------
__device__ int   g_deg [Mn];
__device__ int   g_incl[Mn];
__device__ int   g_off [Mn + 1];
__device__ int   g_cur [Mn];
__device__ int   g_part[256];
__device__ __align__(16) int g_adj [2 * NEmax];
__device__ __half2 g_geneH[(size_t)NGn * 32];
__device__ __half2 g_disH [(size_t)NDn * 32];
__device__ __half2 g_hgH  [(size_t)NGn * 32];
__device__ __half2 g_hdH  [(size_t)NDn * 32];
__device__ __half2 g_mGH  [(size_t)NGn * 32];
__device__ __half2 g_mDH  [(size_t)NDn * 32];

// -------- helpers --------
__device__ __forceinline__ uint32_t packh2(float a, float b) {
    __half2 h = __floats2half2_rn(a, b);
    return *reinterpret_cast<uint32_t*>(&h);
}
__device__ __forceinline__ void mma16(float c[4],
                                      uint32_t a0, uint32_t a1, uint32_t a2, uint32_t a3,
                                      uint32_t b0, uint32_t b1) {
    asm volatile(
        "mma.sync.aligned.m16n8k16.row.col.f32.f16.f16.f32 "
        "{%0,%1,%2,%3},{%4,%5,%6,%7},{%8,%9},{%0,%1,%2,%3};"
        : "+f"(c[0]), "+f"(c[1]), "+f"(c[2]), "+f"(c[3])
        : "r"(a0), "r"(a1), "r"(a2), "r"(a3), "r"(b0), "r"(b1));
}

// -------- fused prologue: zero deg + fp32->fp16 of both embedding tables --------
#define NZ4   (Mn / 4)
#define NG2   (NGn * 32)
#define ND2   (NDn * 32)
__global__ __launch_bounds__(256) void prep_kernel(
    int4* __restrict__ deg4,
    const float2* __restrict__ gene, __half2* __restrict__ geneH,
    const float2* __restrict__ dis,  __half2* __restrict__ disH)
{
    int i = blockIdx.x * blockDim.x + threadIdx.x;
    if (i < NZ4) {
        deg4[i] = make_int4(0, 0, 0, 0);
    } else if (i < NZ4 + NG2) {
        int j = i - NZ4;
        float2 v = gene[j];
        geneH[j] = __floats2half2_rn(v.x, v.y);
    } else if (i < NZ4 + NG2 + ND2) {
        int j = i - NZ4 - NG2;
        float2 v = dis[j];
        disH[j] = __floats2half2_rn(v.x, v.y);
    }
}

// -------- CSR build --------
__global__ void hist_kernel(const int* __restrict__ src, const int* __restrict__ dst,
                            int* __restrict__ deg, int ne) {
    int e = blockIdx.x * blockDim.x + threadIdx.x;
    if (e >= ne) return;
    atomicAdd(&deg[src[e]], 1);
    atomicAdd(&deg[NGn + dst[e]], 1);
}

__global__ __launch_bounds__(1024) void scan1(const int* __restrict__ deg,
                                              int* __restrict__ incl,
                                              int* __restrict__ part, int n) {
    __shared__ int ws[32];
    int i = blockIdx.x * SCAN_B + threadIdx.x;
    int v = (i < n) ? deg[i] : 0;
    int x = v;
    #pragma unroll
    for (int o = 1; o < 32; o <<= 1) {
        int y = __shfl_up_sync(0xFFFFFFFFu, x, o);
        if ((threadIdx.x & 31) >= o) x += y;
    }
    if ((threadIdx.x & 31) == 31) ws[threadIdx.x >> 5] = x;
    __syncthreads();
    if (threadIdx.x < 32) {
        int y = ws[threadIdx.x];
        #pragma unroll
        for (int o = 1; o < 32; o <<= 1) {
            int z = __shfl_up_sync(0xFFFFFFFFu, y, o);
            if (threadIdx.x >= o) y += z;
        }
        ws[threadIdx.x] = y;
    }
    __syncthreads();
    if (threadIdx.x >= 32) x += ws[(threadIdx.x >> 5) - 1];
    if (i < n) incl[i] = x;
    if (threadIdx.x == 1023) part[blockIdx.x] = x;
}

__global__ __launch_bounds__(1024) void scan23(
    const int* __restrict__ incl, const int* __restrict__ deg,
    const int* __restrict__ part,
    int* __restrict__ off, int* __restrict__ cur, int n)
{
    __shared__ int sp[128];
    __shared__ int ws[4];
    int t = threadIdx.x;
    int x = 0, v = 0;
    if (t < 128) {
        v = (t < NBLK) ? part[t] : 0;
        x = v;
        #pragma unroll
        for (int o = 1; o < 32; o <<= 1) {
            int y = __shfl_up_sync(0xFFFFFFFFu, x, o);
            if ((t & 31) >= o) x += y;
        }
        if ((t & 31) == 31) ws[t >> 5] = x;
    }
    __syncthreads();
    if (t < 128) {
        int add = 0;
        for (int w = 0; w < (t >> 5); w++) add += ws[w];
        sp[t] = x + add - v;
    }
    __syncthreads();
    int i = blockIdx.x * SCAN_B + t;
    if (i < n) {
        int inc = incl[i] + sp[blockIdx.x];
        off[i + 1] = inc;
        cur[i] = inc - deg[i];
        if (i == 0) off[0] = 0;
    }
}

__global__ void scatter_kernel(const int* __restrict__ src, const int* __restrict__ dst,
                               int* __restrict__ cur, int* __restrict__ adj, int ne) {
    int e = blockIdx.x * blockDim.x + threadIdx.x;
    if (e >= ne) return;
    int s = src[e], d = dst[e];
    int p = atomicAdd(&cur[s], 1);        adj[p] = d;
    int q = atomicAdd(&cur[NGn + d], 1);  adj[q] = s;
}

// -------- warp-per-node gather-mean, fp16 in/out, fp32 accum, int4 adj --------
__global__ __launch_bounds__(256) void gather_h(
    const __half2* __restrict__ xg, const __half2* __restrict__ xd,
    const int* __restrict__ off, const int* __restrict__ adj,
    __half2* __restrict__ outG, __half2* __restrict__ outD)
{
    int w = (blockIdx.x * blockDim.x + threadIdx.x) >> 5;
    if (w >= Mn) return;
    int lane = threadIdx.x & 31;
    int beg = off[w], end = off[w + 1];
    const __half2* __restrict__ x = (w < NGn) ? xd : xg;
    const int4* __restrict__ adj4 = (const int4*)adj;

    float2 a0 = {0.f, 0.f}, a1 = {0.f, 0.f}, a2 = {0.f, 0.f}, a3 = {0.f, 0.f};
    int j = beg;
    int aligned = (beg + 3) & ~3;
    int pre = (aligned < end) ? aligned : end;
    for (; j < pre; j++) {
        int nn = __ldg(&adj[j]);
        float2 v = __half22float2(x[(size_t)nn * 32 + lane]);
        a0.x += v.x; a0.y += v.y;
    }
    for (; j + 8 <= end; j += 8) {
        int4 q0 = __ldg(&adj4[j >> 2]);
        int4 q1 = __ldg(&adj4[(j >> 2) + 1]);
        float2 v0 = __half22float2(x[(size_t)q0.x * 32 + lane]);
        float2 v1 = __half22float2(x[(size_t)q0.y * 32 + lane]);
        float2 v2 = __half22float2(x[(size_t)q0.z * 32 + lane]);
        float2 v3 = __half22float2(x[(size_t)q0.w * 32 + lane]);
        float2 v4 = __half22float2(x[(size_t)q1.x * 32 + lane]);
        float2 v5 = __half22float2(x[(size_t)q1.y * 32 + lane]);
        float2 v6 = __half22float2(x[(size_t)q1.z * 32 + lane]);
        float2 v7 = __half22float2(x[(size_t)q1.w * 32 + lane]);
        a0.x += v0.x + v4.x; a0.y += v0.y + v4.y;
        a1.x += v1.x + v5.x; a1.y += v1.y + v5.y;
        a2.x += v2.x + v6.x; a2.y += v2.y + v6.y;
        a3.x += v3.x + v7.x; a3.y += v3.y + v7.y;
    }
    if (j + 4 <= end) {
        int4 q = __ldg(&adj4[j >> 2]);
        float2 v0 = __half22float2(x[(size_t)q.x * 32 + lane]);
        float2 v1 = __half22float2(x[(size_t)q.y * 32 + lane]);
        float2 v2 = __half22float2(x[(size_t)q.z * 32 + lane]);
        float2 v3 = __half22float2(x[(size_t)q.w * 32 + lane]);
        a0.x += v0.x; a0.y += v0.y;
        a1.x += v1.x; a1.y += v1.y;
        a2.x += v2.x; a2.y += v2.y;
        a3.x += v3.x; a3.y += v3.y;
        j += 4;
    }
    for (; j < end; j++) {
        int nn = __ldg(&adj[j]);
        float2 v = __half22float2(x[(size_t)nn * 32 + lane]);
        a0.x += v.x; a0.y += v.y;
    }
    float sx = (a0.x + a1.x) + (a2.x + a3.x);
    float sy = (a0.y + a1.y) + (a2.y + a3.y);
    float inv = 1.0f / fmaxf((float)(end - beg), 1.0f);
    __half2 r = __floats2half2_rn(sx * inv, sy * inv);
    if (w < NGn) outG[(size_t)w * 32 + lane] = r;
    else         outD[(size_t)(w - NGn) * 32 + lane] = r;
}

// -------- persistent fused per-layer SAGE linear via fp16 mma (m16n8k16) --------
// Grid is split statically between the D segment and the G segment; each block
// stages its segment's weights ONCE, then grid-strides over that segment's tiles.
// Output fp16 written IN-PLACE over out_h (safe: each warp reads its rows' A
// operands before writing those same rows, and rows are warp-exclusive).
#define LIN_GRID 296
__global__ __launch_bounds__(256) void sage_mma2(
    const __half2* __restrict__ mDh, const __half2* __restrict__ xDh,
    const float* __restrict__ wDl, const float* __restrict__ wDr,
    const float* __restrict__ bDp, __half2* __restrict__ outDh, int nD,
    const __half2* __restrict__ mGh, const __half2* __restrict__ xGh,
    const float* __restrict__ wGl, const float* __restrict__ wGr,
    const float* __restrict__ bGp, __half2* __restrict__ outGh, int nG,
    int relu)
{
    __shared__ uint2 sB[8][8][32];   // 16KB packed fp16 W = [wl; wr]
    __shared__ float sBias[64];

    int nbD = (nD + 127) / 128;
    int nbG = (nG + 127) / 128;
    int split = (int)(((long long)LIN_GRID * nbD) / (nbD + nbG));
    if (split < 1) split = 1;
    bool isD = ((int)blockIdx.x < split);
    const __half2* mean = isD ? mDh : mGh;
    const __half2* x    = isD ? xDh : xGh;
    const float* wl     = isD ? wDl : wGl;
    const float* wr     = isD ? wDr : wGr;
    const float* bias   = isD ? bDp : bGp;
    __half2* out_h      = isD ? outDh : outGh;
    int n               = isD ? nD : nG;
    int nTiles          = isD ? nbD : nbG;
    int blk0            = isD ? blockIdx.x : (blockIdx.x - split);
    int nBlkSeg         = isD ? split : (LIN_GRID - split);

    int tid = threadIdx.x;

    // stage W = [wl; wr] (128 x 64) in fp16 B-fragment order (once per block)
    for (int idx = tid; idx < 8 * 8 * 32; idx += 256) {
        int kc   = idx >> 8;
        int nt   = (idx >> 5) & 7;
        int lane = idx & 31;
        int t = lane & 3, g = lane >> 2;
        int c = nt * 8 + g;
        int k0 = kc * 16;
        int r0 = k0 + 2 * t, r2 = k0 + 2 * t + 8;
        float w00 = (r0 < 64)     ? wl[r0 * 64 + c]       : wr[(r0 - 64) * 64 + c];
        float w01 = (r0 + 1 < 64) ? wl[(r0 + 1) * 64 + c] : wr[(r0 - 63) * 64 + c];
        float w10 = (r2 < 64)     ? wl[r2 * 64 + c]       : wr[(r2 - 64) * 64 + c];
        float w11 = (r2 + 1 < 64) ? wl[(r2 + 1) * 64 + c] : wr[(r2 - 63) * 64 + c];
        sB[kc][nt][lane] = make_uint2(packh2(w00, w01), packh2(w10, w11));
    }
    if (tid < 64) sBias[tid] = bias[tid];
    __syncthreads();

    int warp = tid >> 5, lane = tid & 31;
    int t = lane & 3, g = lane >> 2;
    const uint32_t* meanU = (const uint32_t*)mean;
    const uint32_t* xU    = (const uint32_t*)x;

    for (int blk = blk0; blk < nTiles; blk += nBlkSeg) {
        int row0 = blk * 128 + warp * 16;
        int ra = row0 + g, rb = row0 + 8 + g;
        bool va = ra < n, vb = rb < n;
        size_t raL = (size_t)(va ? ra : 0);
        size_t rbL = (size_t)(vb ? rb : 0);

        float c_[8][4];
        #pragma unroll
        for (int nt = 0; nt < 8; nt++) {
            float b0 = sBias[nt * 8 + 2 * t];
            float b1 = sBias[nt * 8 + 2 * t + 1];
            c_[nt][0] = b0; c_[nt][1] = b1; c_[nt][2] = b0; c_[nt][3] = b1;
        }

        #pragma unroll
        for (int kc = 0; kc < 8; kc++) {
            const uint32_t* __restrict__ A = (kc < 4) ? meanU : xU;
            int base = (kc & 3) * 8;
            uint32_t a0 = __ldg(&A[raL * 32 + base + t]);
            uint32_t a1 = __ldg(&A[rbL * 32 + base + t]);
            uint32_t a2 = __ldg(&A[raL * 32 + base + t + 4]);
            uint32_t a3 = __ldg(&A[rbL * 32 + base + t + 4]);
            #pragma unroll
            for (int nt = 0; nt < 8; nt++) {
                uint2 B = sB[kc][nt][lane];
                mma16(c_[nt], a0, a1, a2, a3, B.x, B.y);
            }
        }

        #pragma unroll
        for (int nt = 0; nt < 8; nt++) {
            float c0 = c_[nt][0], c1 = c_[nt][1], c2 = c_[nt][2], c3 = c_[nt][3];
            if (relu) {
                c0 = fmaxf(c0, 0.f); c1 = fmaxf(c1, 0.f);
                c2 = fmaxf(c2, 0.f); c3 = fmaxf(c3, 0.f);
            }
            if (va) out_h[(size_t)ra * 32 + nt * 4 + t] = __floats2half2_rn(c0, c1);
            if (vb) out_h[(size_t)rb * 32 + nt * 4 + t] = __floats2half2_rn(c2, c3);
        }
    }
}

// -------- label-edge dot product over fp16 rows, fp32 accumulate --------
// 8 lanes per edge; each lane: 1 uint4 (8 halves) per row.
__global__ __launch_bounds__(256) void dot_h(
    const __half2* __restrict__ hg2, const __half2* __restrict__ hd2,
    const int* __restrict__ ls, const int* __restrict__ ld,
    float* __restrict__ out, int nl)
{
    int t = blockIdx.x * blockDim.x + threadIdx.x;
    int e = t >> 3;
    if (e >= nl) return;
    int lane = t & 7;
    int a = ls[e];
    int b = ld[e];
    const uint4* pg = (const uint4*)(hg2 + (size_t)a * 32);
    const uint4* pd = (const uint4*)(hd2 + (size_t)b * 32);
    uint4 G = __ldg(&pg[lane]);
    uint4 D = __ldg(&pd[lane]);

    float acc = 0.f;
    {
        float2 g0 = __half22float2(*(__half2*)&G.x), d0 = __half22float2(*(__half2*)&D.x);
        float2 g1 = __half22float2(*(__half2*)&G.y), d1 = __half22float2(*(__half2*)&D.y);
        float2 g2 = __half22float2(*(__half2*)&G.z), d2 = __half22float2(*(__half2*)&D.z);
        float2 g3 = __half22float2(*(__half2*)&G.w), d3 = __half22float2(*(__half2*)&D.w);
        acc = g0.x * d0.x + g0.y * d0.y + g1.x * d1.x + g1.y * d1.y
            + g2.x * d2.x + g2.y * d2.y + g3.x * d3.x + g3.y * d3.y;
    }
    acc += __shfl_down_sync(0xFFFFFFFFu, acc, 4);
    acc += __shfl_down_sync(0xFFFFFFFFu, acc, 2);
    acc += __shfl_down_sync(0xFFFFFFFFu, acc, 1);
    if (lane == 0) out[e] = acc;
}

extern "C" void kernel_launch(void* const* d_in, const int* in_sizes, int n_in,
                              void* d_out, int out_size)
{
    const float* gene = nullptr;
    const float* dis  = nullptr;
    const float* w[8] = {};
    const float* b[4] = {};
    const int*   edge[2] = {};
    const int*   lab[2]  = {};
    int wi = 0, bi = 0, ei = 0, li = 0;
    int ne = 0, nl = 0;

    for (int i = 0; i < n_in; i++) {
        int sz = in_sizes[i];
        if (sz == NGn * H)          gene = (const float*)d_in[i];
        else if (sz == NDn * H)     dis  = (const float*)d_in[i];
        else if (sz == H * H)       { if (wi < 8) w[wi++] = (const float*)d_in[i]; }
        else if (sz == H)           { if (bi < 4) b[bi++] = (const float*)d_in[i]; }
        else if (sz == 1500000)     { if (ei < 2) { edge[ei++] = (const int*)d_in[i]; ne = sz; } }
        else if (sz == 500000)      { if (li < 2) { lab[li++]  = (const int*)d_in[i]; nl = sz; } }
    }

    int *deg, *incl, *off, *cur, *part, *adj;
    __half2 *geneH, *disH, *hgH, *hdH, *mGH, *mDH;
    cudaGetSymbolAddress((void**)&deg,   g_deg);
    cudaGetSymbolAddress((void**)&incl,  g_incl);
    cudaGetSymbolAddress((void**)&off,   g_off);
    cudaGetSymbolAddress((void**)&cur,   g_cur);
    cudaGetSymbolAddress((void**)&part,  g_part);
    cudaGetSymbolAddress((void**)&adj,   g_adj);
    cudaGetSymbolAddress((void**)&geneH, g_geneH);
    cudaGetSymbolAddress((void**)&disH,  g_disH);
    cudaGetSymbolAddress((void**)&hgH,   g_hgH);
    cudaGetSymbolAddress((void**)&hdH,   g_hdH);
    cudaGetSymbolAddress((void**)&mGH,   g_mGH);
    cudaGetSymbolAddress((void**)&mDH,   g_mDH);

    int egrid = (ne + 255) / 256;
    int ggrid = (Mn * 32 + 255) / 256;
    int prep_items = NZ4 + NG2 + ND2;

    // ---- prologue + CSR build ----
    prep_kernel<<<(prep_items + 255) / 256, 256>>>(
        (int4*)deg, (const float2*)gene, geneH, (const float2*)dis, disH);
    hist_kernel<<<egrid, 256>>>(edge[0], edge[1], deg, ne);
    scan1<<<NBLK, 1024>>>(deg, incl, part, Mn);
    scan23<<<NBLK, 1024>>>(incl, deg, part, off, cur, Mn);
    scatter_kernel<<<egrid, 256>>>(edge[0], edge[1], cur, adj, ne);

    // ---- layer 1 ----
    gather_h<<<ggrid, 256>>>(geneH, disH, off, adj, mGH, mDH);
    sage_mma2<<<LIN_GRID, 256>>>(mDH, disH, w[0], w[1], b[0], hdH, NDn,
                                 mGH, geneH, w[2], w[3], b[1], hgH, NGn, 1);

    // ---- layer 2 (fp16 outputs written in-place over hgH/hdH) ----
    gather_h<<<ggrid, 256>>>(hgH, hdH, off, adj, mGH, mDH);
    sage_mma2<<<LIN_GRID, 256>>>(mDH, hdH, w[4], w[5], b[2], hdH, NDn,
                                 mGH, hgH, w[6], w[7], b[3], hgH, NGn, 0);

    // ---- classifier (fp16 rows, fp32 accumulate) ----
    int dot_grid = (nl * 8 + 255) / 256;
    dot_h<<<dot_grid, 256>>>(hgH, hdH, lab[0], lab[1], (float*)d_out, nl);
}

// round 7
// speedup vs baseline: 2.5642x; 1.1690x over previous
#include <cuda_runtime.h>
#include <cuda_fp16.h>
#include <cstddef>
#include <cstdint>

#define H 64
#define NGn 100000
#define NDn 30000
#define Mn (NGn + NDn)
#define NEmax 1500000
#define SCAN_B 1024
#define NBLK ((Mn + SCAN_B - 1) / SCAN_B)   // 127

// -------- scratch --------
__device__ int   g_deg [Mn];
__device__ int   g_incl[Mn];
__device__ int   g_off [Mn + 1];
__device__ int   g_cur [Mn];
__device__ int   g_part[256];
__device__ __align__(16) int g_adj [2 * NEmax];
__device__ __half2 g_geneH[(size_t)NGn * 32];
__device__ __half2 g_disH [(size_t)NDn * 32];
__device__ __half2 g_hgH  [(size_t)NGn * 32];
__device__ __half2 g_hdH  [(size_t)NDn * 32];
__device__ __half2 g_mGH  [(size_t)NGn * 32];
__device__ __half2 g_mDH  [(size_t)NDn * 32];

// -------- helpers --------
__device__ __forceinline__ uint32_t packh2(float a, float b) {
    __half2 h = __floats2half2_rn(a, b);
    return *reinterpret_cast<uint32_t*>(&h);
}
__device__ __forceinline__ void mma16(float c[4],
                                      uint32_t a0, uint32_t a1, uint32_t a2, uint32_t a3,
                                      uint32_t b0, uint32_t b1) {
    asm volatile(
        "mma.sync.aligned.m16n8k16.row.col.f32.f16.f16.f32 "
        "{%0,%1,%2,%3},{%4,%5,%6,%7},{%8,%9},{%0,%1,%2,%3};"
        : "+f"(c[0]), "+f"(c[1]), "+f"(c[2]), "+f"(c[3])
        : "r"(a0), "r"(a1), "r"(a2), "r"(a3), "r"(b0), "r"(b1));
}
__device__ __forceinline__ void acc_u4(float2& a0, float2& a1, float2& a2, float2& a3,
                                       uint4 v) {
    const __half2* h = (const __half2*)&v;
    float2 f0 = __half22float2(h[0]);
    float2 f1 = __half22float2(h[1]);
    float2 f2 = __half22float2(h[2]);
    float2 f3 = __half22float2(h[3]);
    a0.x += f0.x; a0.y += f0.y;
    a1.x += f1.x; a1.y += f1.y;
    a2.x += f2.x; a2.y += f2.y;
    a3.x += f3.x; a3.y += f3.y;
}

// -------- fused prologue: zero deg + fp32->fp16 of both embedding tables --------
#define NZ4   (Mn / 4)
#define NG2   (NGn * 32)
#define ND2   (NDn * 32)
__global__ __launch_bounds__(256) void prep_kernel(
    int4* __restrict__ deg4,
    const float2* __restrict__ gene, __half2* __restrict__ geneH,
    const float2* __restrict__ dis,  __half2* __restrict__ disH)
{
    int i = blockIdx.x * blockDim.x + threadIdx.x;
    if (i < NZ4) {
        deg4[i] = make_int4(0, 0, 0, 0);
    } else if (i < NZ4 + NG2) {
        int j = i - NZ4;
        float2 v = gene[j];
        geneH[j] = __floats2half2_rn(v.x, v.y);
    } else if (i < NZ4 + NG2 + ND2) {
        int j = i - NZ4 - NG2;
        float2 v = dis[j];
        disH[j] = __floats2half2_rn(v.x, v.y);
    }
}

// -------- CSR build --------
__global__ void hist_kernel(const int* __restrict__ src, const int* __restrict__ dst,
                            int* __restrict__ deg, int ne) {
    int e = blockIdx.x * blockDim.x + threadIdx.x;
    if (e >= ne) return;
    atomicAdd(&deg[src[e]], 1);
    atomicAdd(&deg[NGn + dst[e]], 1);
}

__global__ __launch_bounds__(1024) void scan1(const int* __restrict__ deg,
                                              int* __restrict__ incl,
                                              int* __restrict__ part, int n) {
    __shared__ int ws[32];
    int i = blockIdx.x * SCAN_B + threadIdx.x;
    int v = (i < n) ? deg[i] : 0;
    int x = v;
    #pragma unroll
    for (int o = 1; o < 32; o <<= 1) {
        int y = __shfl_up_sync(0xFFFFFFFFu, x, o);
        if ((threadIdx.x & 31) >= o) x += y;
    }
    if ((threadIdx.x & 31) == 31) ws[threadIdx.x >> 5] = x;
    __syncthreads();
    if (threadIdx.x < 32) {
        int y = ws[threadIdx.x];
        #pragma unroll
        for (int o = 1; o < 32; o <<= 1) {
            int z = __shfl_up_sync(0xFFFFFFFFu, y, o);
            if (threadIdx.x >= o) y += z;
        }
        ws[threadIdx.x] = y;
    }
    __syncthreads();
    if (threadIdx.x >= 32) x += ws[(threadIdx.x >> 5) - 1];
    if (i < n) incl[i] = x;
    if (threadIdx.x == 1023) part[blockIdx.x] = x;
}

__global__ __launch_bounds__(1024) void scan23(
    const int* __restrict__ incl, const int* __restrict__ deg,
    const int* __restrict__ part,
    int* __restrict__ off, int* __restrict__ cur, int n)
{
    __shared__ int sp[128];
    __shared__ int ws[4];
    int t = threadIdx.x;
    int x = 0, v = 0;
    if (t < 128) {
        v = (t < NBLK) ? part[t] : 0;
        x = v;
        #pragma unroll
        for (int o = 1; o < 32; o <<= 1) {
            int y = __shfl_up_sync(0xFFFFFFFFu, x, o);
            if ((t & 31) >= o) x += y;
        }
        if ((t & 31) == 31) ws[t >> 5] = x;
    }
    __syncthreads();
    if (t < 128) {
        int add = 0;
        for (int w = 0; w < (t >> 5); w++) add += ws[w];
        sp[t] = x + add - v;
    }
    __syncthreads();
    int i = blockIdx.x * SCAN_B + t;
    if (i < n) {
        int inc = incl[i] + sp[blockIdx.x];
        off[i + 1] = inc;
        cur[i] = inc - deg[i];
        if (i == 0) off[0] = 0;
    }
}

__global__ void scatter_kernel(const int* __restrict__ src, const int* __restrict__ dst,
                               int* __restrict__ cur, int* __restrict__ adj, int ne) {
    int e = blockIdx.x * blockDim.x + threadIdx.x;
    if (e >= ne) return;
    int s = src[e], d = dst[e];
    int p = atomicAdd(&cur[s], 1);        adj[p] = d;
    int q = atomicAdd(&cur[NGn + d], 1);  adj[q] = s;
}

// -------- warp-per-node gather-mean: 8-lane groups cover full rows (uint4) --------
// lane = g*8 + l: group g handles neighbors j+g (4 per step); sublane l covers
// 16B of the 128B row. One LDG.128 per 4 neighbor rows.
__global__ __launch_bounds__(256) void gather_h(
    const uint4* __restrict__ xg4, const uint4* __restrict__ xd4,
    const int* __restrict__ off, const int* __restrict__ adj,
    uint4* __restrict__ outG, uint4* __restrict__ outD)
{
    int w = (blockIdx.x * blockDim.x + threadIdx.x) >> 5;
    if (w >= Mn) return;
    int lane = threadIdx.x & 31;
    int g = lane >> 3, l = lane & 7;
    int beg = off[w], end = off[w + 1];
    const uint4* __restrict__ x4 = (w < NGn) ? xd4 : xg4;

    float2 a0 = {0.f, 0.f}, a1 = {0.f, 0.f}, a2 = {0.f, 0.f}, a3 = {0.f, 0.f};
    int deg = end - beg;
    if (deg > 0) {
        int j = beg;
        for (; j + 8 <= end; j += 8) {
            int n0 = __ldg(&adj[j + g]);
            int n1 = __ldg(&adj[j + 4 + g]);
            uint4 v0 = __ldg(&x4[(size_t)n0 * 8 + l]);
            uint4 v1 = __ldg(&x4[(size_t)n1 * 8 + l]);
            acc_u4(a0, a1, a2, a3, v0);
            acc_u4(a0, a1, a2, a3, v1);
        }
        for (; j < end; j += 4) {
            int k = j + g;
            bool p = k < end;
            int nn = __ldg(&adj[p ? k : beg]);
            uint4 v = __ldg(&x4[(size_t)nn * 8 + l]);
            if (p) acc_u4(a0, a1, a2, a3, v);
        }
    }
    // reduce the 4 group partials (butterfly over lanes differing in bits 3,4)
    #pragma unroll
    for (int o = 8; o <= 16; o <<= 1) {
        a0.x += __shfl_xor_sync(0xFFFFFFFFu, a0.x, o);
        a0.y += __shfl_xor_sync(0xFFFFFFFFu, a0.y, o);
        a1.x += __shfl_xor_sync(0xFFFFFFFFu, a1.x, o);
        a1.y += __shfl_xor_sync(0xFFFFFFFFu, a1.y, o);
        a2.x += __shfl_xor_sync(0xFFFFFFFFu, a2.x, o);
        a2.y += __shfl_xor_sync(0xFFFFFFFFu, a2.y, o);
        a3.x += __shfl_xor_sync(0xFFFFFFFFu, a3.x, o);
        a3.y += __shfl_xor_sync(0xFFFFFFFFu, a3.y, o);
    }
    if (g == 0) {
        float inv = 1.0f / fmaxf((float)deg, 1.0f);
        uint4 o;
        o.x = packh2(a0.x * inv, a0.y * inv);
        o.y = packh2(a1.x * inv, a1.y * inv);
        o.z = packh2(a2.x * inv, a2.y * inv);
        o.w = packh2(a3.x * inv, a3.y * inv);
        if (w < NGn) outG[(size_t)w * 8 + l] = o;
        else         outD[(size_t)(w - NGn) * 8 + l] = o;
    }
}

// -------- persistent fused per-layer SAGE linear via fp16 mma (m16n8k16) --------
#define LIN_GRID 296
__global__ __launch_bounds__(256) void sage_mma2(
    const __half2* __restrict__ mDh, const __half2* __restrict__ xDh,
    const float* __restrict__ wDl, const float* __restrict__ wDr,
    const float* __restrict__ bDp, __half2* __restrict__ outDh, int nD,
    const __half2* __restrict__ mGh, const __half2* __restrict__ xGh,
    const float* __restrict__ wGl, const float* __restrict__ wGr,
    const float* __restrict__ bGp, __half2* __restrict__ outGh, int nG,
    int relu)
{
    __shared__ uint2 sB[8][8][32];   // 16KB packed fp16 W = [wl; wr]
    __shared__ float sBias[64];

    int nbD = (nD + 127) / 128;
    int nbG = (nG + 127) / 128;
    int split = (int)(((long long)LIN_GRID * nbD) / (nbD + nbG));
    if (split < 1) split = 1;
    bool isD = ((int)blockIdx.x < split);
    const __half2* mean = isD ? mDh : mGh;
    const __half2* x    = isD ? xDh : xGh;
    const float* wl     = isD ? wDl : wGl;
    const float* wr     = isD ? wDr : wGr;
    const float* bias   = isD ? bDp : bGp;
    __half2* out_h      = isD ? outDh : outGh;
    int n               = isD ? nD : nG;
    int nTiles          = isD ? nbD : nbG;
    int blk0            = isD ? blockIdx.x : (blockIdx.x - split);
    int nBlkSeg         = isD ? split : (LIN_GRID - split);

    int tid = threadIdx.x;

    for (int idx = tid; idx < 8 * 8 * 32; idx += 256) {
        int kc   = idx >> 8;
        int nt   = (idx >> 5) & 7;
        int lane = idx & 31;
        int t = lane & 3, g = lane >> 2;
        int c = nt * 8 + g;
        int k0 = kc * 16;
        int r0 = k0 + 2 * t, r2 = k0 + 2 * t + 8;
        float w00 = (r0 < 64)     ? wl[r0 * 64 + c]       : wr[(r0 - 64) * 64 + c];
        float w01 = (r0 + 1 < 64) ? wl[(r0 + 1) * 64 + c] : wr[(r0 - 63) * 64 + c];
        float w10 = (r2 < 64)     ? wl[r2 * 64 + c]       : wr[(r2 - 64) * 64 + c];
        float w11 = (r2 + 1 < 64) ? wl[(r2 + 1) * 64 + c] : wr[(r2 - 63) * 64 + c];
        sB[kc][nt][lane] = make_uint2(packh2(w00, w01), packh2(w10, w11));
    }
    if (tid < 64) sBias[tid] = bias[tid];
    __syncthreads();

    int warp = tid >> 5, lane = tid & 31;
    int t = lane & 3, g = lane >> 2;
    const uint32_t* meanU = (const uint32_t*)mean;
    const uint32_t* xU    = (const uint32_t*)x;

    for (int blk = blk0; blk < nTiles; blk += nBlkSeg) {
        int row0 = blk * 128 + warp * 16;
        int ra = row0 + g, rb = row0 + 8 + g;
        bool va = ra < n, vb = rb < n;
        size_t raL = (size_t)(va ? ra : 0);
        size_t rbL = (size_t)(vb ? rb : 0);

        float c_[8][4];
        #pragma unroll
        for (int nt = 0; nt < 8; nt++) {
            float b0 = sBias[nt * 8 + 2 * t];
            float b1 = sBias[nt * 8 + 2 * t + 1];
            c_[nt][0] = b0; c_[nt][1] = b1; c_[nt][2] = b0; c_[nt][3] = b1;
        }

        #pragma unroll
        for (int kc = 0; kc < 8; kc++) {
            const uint32_t* __restrict__ A = (kc < 4) ? meanU : xU;
            int base = (kc & 3) * 8;
            uint32_t a0 = __ldg(&A[raL * 32 + base + t]);
            uint32_t a1 = __ldg(&A[rbL * 32 + base + t]);
            uint32_t a2 = __ldg(&A[raL * 32 + base + t + 4]);
            uint32_t a3 = __ldg(&A[rbL * 32 + base + t + 4]);
            #pragma unroll
            for (int nt = 0; nt < 8; nt++) {
                uint2 B = sB[kc][nt][lane];
                mma16(c_[nt], a0, a1, a2, a3, B.x, B.y);
            }
        }

        #pragma unroll
        for (int nt = 0; nt < 8; nt++) {
            float c0 = c_[nt][0], c1 = c_[nt][1], c2 = c_[nt][2], c3 = c_[nt][3];
            if (relu) {
                c0 = fmaxf(c0, 0.f); c1 = fmaxf(c1, 0.f);
                c2 = fmaxf(c2, 0.f); c3 = fmaxf(c3, 0.f);
            }
            if (va) out_h[(size_t)ra * 32 + nt * 4 + t] = __floats2half2_rn(c0, c1);
            if (vb) out_h[(size_t)rb * 32 + nt * 4 + t] = __floats2half2_rn(c2, c3);
        }
    }
}

// -------- label-edge dot product over fp16 rows, fp32 accumulate --------
__global__ __launch_bounds__(256) void dot_h(
    const __half2* __restrict__ hg2, const __half2* __restrict__ hd2,
    const int* __restrict__ ls, const int* __restrict__ ld,
    float* __restrict__ out, int nl)
{
    int t = blockIdx.x * blockDim.x + threadIdx.x;
    int e = t >> 3;
    if (e >= nl) return;
    int lane = t & 7;
    int a = ls[e];
    int b = ld[e];
    const uint4* pg = (const uint4*)(hg2 + (size_t)a * 32);
    const uint4* pd = (const uint4*)(hd2 + (size_t)b * 32);
    uint4 G = __ldg(&pg[lane]);
    uint4 D = __ldg(&pd[lane]);

    float acc = 0.f;
    {
        float2 g0 = __half22float2(*(__half2*)&G.x), d0 = __half22float2(*(__half2*)&D.x);
        float2 g1 = __half22float2(*(__half2*)&G.y), d1 = __half22float2(*(__half2*)&D.y);
        float2 g2 = __half22float2(*(__half2*)&G.z), d2 = __half22float2(*(__half2*)&D.z);
        float2 g3 = __half22float2(*(__half2*)&G.w), d3 = __half22float2(*(__half2*)&D.w);
        acc = g0.x * d0.x + g0.y * d0.y + g1.x * d1.x + g1.y * d1.y
            + g2.x * d2.x + g2.y * d2.y + g3.x * d3.x + g3.y * d3.y;
    }
    acc += __shfl_down_sync(0xFFFFFFFFu, acc, 4);
    acc += __shfl_down_sync(0xFFFFFFFFu, acc, 2);
    acc += __shfl_down_sync(0xFFFFFFFFu, acc, 1);
    if (lane == 0) out[e] = acc;
}

extern "C" void kernel_launch(void* const* d_in, const int* in_sizes, int n_in,
                              void* d_out, int out_size)
{
    const float* gene = nullptr;
    const float* dis  = nullptr;
    const float* w[8] = {};
    const float* b[4] = {};
    const int*   edge[2] = {};
    const int*   lab[2]  = {};
    int wi = 0, bi = 0, ei = 0, li = 0;
    int ne = 0, nl = 0;

    for (int i = 0; i < n_in; i++) {
        int sz = in_sizes[i];
        if (sz == NGn * H)          gene = (const float*)d_in[i];
        else if (sz == NDn * H)     dis  = (const float*)d_in[i];
        else if (sz == H * H)       { if (wi < 8) w[wi++] = (const float*)d_in[i]; }
        else if (sz == H)           { if (bi < 4) b[bi++] = (const float*)d_in[i]; }
        else if (sz == 1500000)     { if (ei < 2) { edge[ei++] = (const int*)d_in[i]; ne = sz; } }
        else if (sz == 500000)      { if (li < 2) { lab[li++]  = (const int*)d_in[i]; nl = sz; } }
    }

    int *deg, *incl, *off, *cur, *part, *adj;
    __half2 *geneH, *disH, *hgH, *hdH, *mGH, *mDH;
    cudaGetSymbolAddress((void**)&deg,   g_deg);
    cudaGetSymbolAddress((void**)&incl,  g_incl);
    cudaGetSymbolAddress((void**)&off,   g_off);
    cudaGetSymbolAddress((void**)&cur,   g_cur);
    cudaGetSymbolAddress((void**)&part,  g_part);
    cudaGetSymbolAddress((void**)&adj,   g_adj);
    cudaGetSymbolAddress((void**)&geneH, g_geneH);
    cudaGetSymbolAddress((void**)&disH,  g_disH);
    cudaGetSymbolAddress((void**)&hgH,   g_hgH);
    cudaGetSymbolAddress((void**)&hdH,   g_hdH);
    cudaGetSymbolAddress((void**)&mGH,   g_mGH);
    cudaGetSymbolAddress((void**)&mDH,   g_mDH);

    int egrid = (ne + 255) / 256;
    int ggrid = (Mn * 32 + 255) / 256;
    int prep_items = NZ4 + NG2 + ND2;

    // ---- prologue + CSR build ----
    prep_kernel<<<(prep_items + 255) / 256, 256>>>(
        (int4*)deg, (const float2*)gene, geneH, (const float2*)dis, disH);
    hist_kernel<<<egrid, 256>>>(edge[0], edge[1], deg, ne);
    scan1<<<NBLK, 1024>>>(deg, incl, part, Mn);
    scan23<<<NBLK, 1024>>>(incl, deg, part, off, cur, Mn);
    scatter_kernel<<<egrid, 256>>>(edge[0], edge[1], cur, adj, ne);

    // ---- layer 1 ----
    gather_h<<<ggrid, 256>>>((const uint4*)geneH, (const uint4*)disH, off, adj,
                             (uint4*)mGH, (uint4*)mDH);
    sage_mma2<<<LIN_GRID, 256>>>(mDH, disH, w[0], w[1], b[0], hdH, NDn,
                                 mGH, geneH, w[2], w[3], b[1], hgH, NGn, 1);

    // ---- layer 2 (fp16 outputs written in-place over hgH/hdH) ----
    gather_h<<<ggrid, 256>>>((const uint4*)hgH, (const uint4*)hdH, off, adj,
                             (uint4*)mGH, (uint4*)mDH);
    sage_mma2<<<LIN_GRID, 256>>>(mDH, hdH, w[4], w[5], b[2], hdH, NDn,
                                 mGH, hgH, w[6], w[7], b[3], hgH, NGn, 0);

    // ---- classifier (fp16 rows, fp32 accumulate) ----
    int dot_grid = (nl * 8 + 255) / 256;
    dot_h<<<dot_grid, 256>>>(hgH, hdH, lab[0], lab[1], (float*)d_out, nl);
}